// round 13
// baseline (speedup 1.0000x reference)
#include <cuda_runtime.h>
#include <cuda_bf16.h>
#include <math.h>
#include <stdint.h>

#define NB 4
#define NS 2048
#define ND 1024
#define NH 16
#define NHD 64
#define NTOK (NB*NS)

// ---------------- device global scratch (allocation-free) ----------------
// packed unit = 16B = {hi pair_t, hi pair_{t+4}, lo pair_t, lo pair_{t+4}}
__device__ uint4 g_Xp [(size_t)NTOK*64*4];        // X packed
__device__ uint4 g_Wp [(size_t)3*ND*64*4];        // wq|wk|wv packed
__device__ uint4 g_WOp[(size_t)ND*64*4];          // wo packed
__device__ uint4 g_Qp [(size_t)NB*NH*NS*16];      // Q packed
__device__ uint4 g_Kp [(size_t)NB*NH*NS*16];      // K packed
__device__ float g_V  [(size_t)NB*NH*NS*NHD];     // V fp32 (tf32-rounded), [bh][s][d]
__device__ float2 g_Vt[(size_t)NB*NH*64*1024];    // V^T paired: [bh][d][1024] pairs
__device__ uint4 g_AOp[(size_t)NTOK*64*4];        // attention out packed

// ---------------- helpers ----------------
__device__ __forceinline__ uint32_t smem_u32(const void* p){
    uint32_t a;
    asm("{ .reg .u64 t; cvta.to.shared.u64 t, %1; cvt.u32.u64 %0, t; }" : "=r"(a) : "l"(p));
    return a;
}
__device__ __forceinline__ float tf32r(float x){
    uint32_t y; asm("cvt.rna.tf32.f32 %0, %1;" : "=r"(y) : "f"(x));
    return __uint_as_float(y);
}
__device__ __forceinline__ void mma8(float c[4], const float a[4], const float b[2]){
    asm volatile(
      "mma.sync.aligned.m16n8k8.row.col.f32.tf32.tf32.f32 "
      "{%0,%1,%2,%3}, {%4,%5,%6,%7}, {%8,%9}, {%0,%1,%2,%3};\n"
      : "+f"(c[0]),"+f"(c[1]),"+f"(c[2]),"+f"(c[3])
      : "r"(__float_as_uint(a[0])),"r"(__float_as_uint(a[1])),
        "r"(__float_as_uint(a[2])),"r"(__float_as_uint(a[3])),
        "r"(__float_as_uint(b[0])),"r"(__float_as_uint(b[1])));
}
__device__ __forceinline__ void mmabf(float c[4], const uint32_t a[4], const uint32_t b[2]){
    asm volatile(
      "mma.sync.aligned.m16n8k16.row.col.f32.bf16.bf16.f32 "
      "{%0,%1,%2,%3}, {%4,%5,%6,%7}, {%8,%9}, {%0,%1,%2,%3};\n"
      : "+f"(c[0]),"+f"(c[1]),"+f"(c[2]),"+f"(c[3])
      : "r"(a[0]),"r"(a[1]),"r"(a[2]),"r"(a[3]), "r"(b[0]),"r"(b[1]));
}
__device__ __forceinline__ void cpa16(uint32_t saddr, const void* gaddr){
    asm volatile("cp.async.cg.shared.global [%0], [%1], 16;" :: "r"(saddr), "l"(gaddr) : "memory");
}
#define CP_COMMIT() asm volatile("cp.async.commit_group;" ::: "memory")
#define CP_WAIT(n)  asm volatile("cp.async.wait_group %0;" :: "n"(n) : "memory")

__device__ __forceinline__ uint32_t packbf2(__nv_bfloat16 a, __nv_bfloat16 b){
    return (uint32_t)__bfloat16_as_ushort(a) | ((uint32_t)__bfloat16_as_ushort(b) << 16);
}
__device__ __forceinline__ void bfsplit2(float a, float b, uint32_t& hi, uint32_t& lo){
    __nv_bfloat16 ha = __float2bfloat16(a), hb = __float2bfloat16(b);
    hi = packbf2(ha, hb);
    lo = packbf2(__float2bfloat16(a - __bfloat162float(ha)),
                 __float2bfloat16(b - __bfloat162float(hb)));
}

// ---------------------------------------------------------------------------
// prep: one thread packs one k16 chunk
// ---------------------------------------------------------------------------
__device__ __forceinline__ void pack_chunk(const float* src, uint4* dst){
    float x[16];
    #pragma unroll
    for (int i=0;i<4;i++){ float4 v = *(const float4*)(src + i*4);
        x[i*4]=v.x; x[i*4+1]=v.y; x[i*4+2]=v.z; x[i*4+3]=v.w; }
    uint32_t hi[8], lo[8];
    #pragma unroll
    for (int j=0;j<8;j++) bfsplit2(x[2*j], x[2*j+1], hi[j], lo[j]);
    #pragma unroll
    for (int u=0;u<4;u++) dst[u] = make_uint4(hi[u], hi[u+4], lo[u], lo[u+4]);
}

__global__ __launch_bounds__(256) void prep_x(const float* __restrict__ X){
    int i = blockIdx.x*256 + threadIdx.x;
    pack_chunk(X + (size_t)i*16, g_Xp + (size_t)i*4);
}

__global__ __launch_bounds__(256) void prep_w(
    const float* __restrict__ wq, const float* __restrict__ wk,
    const float* __restrict__ wv, const float* __restrict__ wo){
    int i = blockIdx.x*256 + threadIdx.x;
    if (i < 3*ND*64){
        int row = i >> 6, c = i & 63;
        int which = row >> 10, r = row & 1023;
        const float* src = (which==0)? wq : (which==1)? wk : wv;
        pack_chunk(src + (size_t)r*ND + c*16, g_Wp + (size_t)i*4);
    } else {
        int j = i - 3*ND*64;
        int row = j >> 6, c = j & 63;
        pack_chunk(wo + (size_t)row*ND + c*16, g_WOp + (size_t)j*4);
    }
}

// ---------------------------------------------------------------------------
// V transpose: g_V [bh][s][d] -> g_Vt [bh][d] paired along s.
// ---------------------------------------------------------------------------
__global__ __launch_bounds__(128) void transp_v(){
    __shared__ float Vs[64*65];
    const int tid = threadIdx.x;
    const int t3 = blockIdx.x, h = blockIdx.y, b = blockIdx.z;
    const size_t bh = (size_t)(b*NH + h);
    const float* src = g_V + (bh*NS + (size_t)t3*64)*64;
    #pragma unroll
    for (int i=0;i<8;i++){
        int idx = i*128 + tid, row = idx>>4, c4 = idx&15;
        float4 v = *(const float4*)(src + row*64 + c4*4);
        Vs[row*65 + c4*4+0]=v.x; Vs[row*65 + c4*4+1]=v.y;
        Vs[row*65 + c4*4+2]=v.z; Vs[row*65 + c4*4+3]=v.w;
    }
    __syncthreads();
    float2* dst = g_Vt + bh*64*1024;
    #pragma unroll
    for (int i=0;i<16;i++){
        int idx = i*128 + tid;
        int t = idx&3, jl = (idx>>2)&7, d = idx>>5;
        int s = jl*8 + t;
        dst[(size_t)d*1024 + (t3*8 + jl)*4 + t] =
            make_float2(Vs[s*65 + d], Vs[(s+4)*65 + d]);
    }
}

// ---------------------------------------------------------------------------
// GEMM: C[128x128] = A[128x1024] * B[128x1024]^T, bf16x2 3-term.
// 8 warps (256 thr), warp tile 64x32. 4-stage cp.async pipeline, k-tile=16
// (one packed chunk). Stage = 20480B: A rows 80B stride (5 16B-units, 5 coprime
// 8 -> conflict-free LDS.128 phases), B at +10240. One bar per iter.
// mode 0: RMS(+scale)+RoPE epilogue (cross-warp RMS via smem red buffer)
// mode 1: plain store
// ---------------------------------------------------------------------------
#define GSTAGE 20480
#define GEMM_SMEM (4*GSTAGE)

__global__ void __launch_bounds__(256, 2) gemm128(
    int mode,
    const float* __restrict__ cosp, const float* __restrict__ sinp,
    const float* __restrict__ qsc,  const float* __restrict__ ksc,
    float* __restrict__ outp)
{
    extern __shared__ __align__(16) char dsm[];
    const int tid = threadIdx.x, lane = tid & 31, w = tid >> 5;
    const int lg = lane >> 2, tg = lane & 3;
    const int wm = w >> 2, wn = w & 3;
    const int tok0 = blockIdx.x * 128;
    const int nt = blockIdx.y;
    const int brow0 = nt * 128;
    const uint32_t sdyn = smem_u32(dsm);

    const uint4* Aunits = mode ? g_AOp : g_Xp;
    const uint4* Bunits = mode ? g_WOp : g_Wp;

    float c[4][4][4];
    #pragma unroll
    for (int mi=0;mi<4;mi++)
      #pragma unroll
      for (int ni=0;ni<4;ni++)
        #pragma unroll
        for (int q=0;q<4;q++) c[mi][ni][q]=0.f;

    // issue one k16 chunk (stage = ck & 3)
    #define G_ISSUE(ck) do { \
        uint32_t sa = sdyn + ((ck)&3)*GSTAGE; \
        uint32_t sb = sa + 10240; \
        _Pragma("unroll") \
        for (int i=0;i<2;i++){ \
            int idx = i*256 + tid; \
            int u = idx&3, row = idx>>2; \
            cpa16(sa + row*80 + u*16, \
                  Aunits + ((size_t)(tok0+row)*64 + (ck))*4 + u); \
            cpa16(sb + row*80 + u*16, \
                  Bunits + ((size_t)(brow0+row)*64 + (ck))*4 + u); \
        } \
        CP_COMMIT(); \
    } while(0)

    G_ISSUE(0); G_ISSUE(1); G_ISSUE(2);
    for (int ck = 0; ck < 64; ++ck){
        if (ck < 62)      CP_WAIT(2);
        else if (ck == 62) CP_WAIT(1);
        else              CP_WAIT(0);
        __syncthreads();
        if (ck + 3 < 64) G_ISSUE(ck+3);

        const char* pA = dsm + (ck&3)*GSTAGE;
        const char* pB = pA + 10240;
        uint32_t ah[4][4], al[4][4];
        #pragma unroll
        for (int mi=0;mi<4;mi++){
            int r = wm*64 + mi*16 + lg;
            uint4 u0 = *(const uint4*)(pA + r*80 + tg*16);
            uint4 u1 = *(const uint4*)(pA + (r+8)*80 + tg*16);
            ah[mi][0]=u0.x; ah[mi][1]=u1.x; ah[mi][2]=u0.y; ah[mi][3]=u1.y;
            al[mi][0]=u0.z; al[mi][1]=u1.z; al[mi][2]=u0.w; al[mi][3]=u1.w;
        }
        #pragma unroll
        for (int ni=0;ni<4;ni++){
            int r = wn*32 + ni*8 + lg;
            uint4 bu = *(const uint4*)(pB + r*80 + tg*16);
            uint32_t bh[2] = {bu.x, bu.y};
            uint32_t bl[2] = {bu.z, bu.w};
            #pragma unroll
            for (int mi=0;mi<4;mi++){
                mmabf(c[mi][ni], ah[mi], bh);
                mmabf(c[mi][ni], ah[mi], bl);
                mmabf(c[mi][ni], al[mi], bh);
            }
        }
    }
    #undef G_ISSUE

    if (mode == 1){
        #pragma unroll
        for (int mi=0;mi<4;mi++)
          #pragma unroll
          for (int half=0; half<2; ++half){
            int token = tok0 + wm*64 + mi*16 + half*8 + lg;
            float* dst = outp + (size_t)token*ND + nt*128 + wn*32;
            #pragma unroll
            for (int ni=0;ni<4;ni++)
                *(float2*)(dst + ni*8 + 2*tg) =
                    make_float2(c[mi][ni][half*2], c[mi][ni][half*2+1]);
          }
        return;
    }

    // ---- mode 0: cross-warp RMS (warp wn pairs with wn^1 over the same head) ----
    __syncthreads();
    float* red = (float*)dsm;              // [128][4]
    float part[4][2];
    #pragma unroll
    for (int mi=0;mi<4;mi++){
        float s0=0.f, s1=0.f;
        #pragma unroll
        for (int ni=0;ni<4;ni++){
            s0 += c[mi][ni][0]*c[mi][ni][0] + c[mi][ni][1]*c[mi][ni][1];
            s1 += c[mi][ni][2]*c[mi][ni][2] + c[mi][ni][3]*c[mi][ni][3];
        }
        s0 += __shfl_xor_sync(0xffffffffu, s0, 1);
        s0 += __shfl_xor_sync(0xffffffffu, s0, 2);
        s1 += __shfl_xor_sync(0xffffffffu, s1, 1);
        s1 += __shfl_xor_sync(0xffffffffu, s1, 2);
        part[mi][0]=s0; part[mi][1]=s1;
        if (tg == 0){
            red[(wm*64 + mi*16 + lg)*4 + wn]     = s0;
            red[(wm*64 + mi*16 + 8 + lg)*4 + wn] = s1;
        }
    }
    __syncthreads();
    float rs[4][2];
    #pragma unroll
    for (int mi=0;mi<4;mi++)
      #pragma unroll
      for (int half=0; half<2; ++half){
        int row = wm*64 + mi*16 + half*8 + lg;
        float tot = part[mi][half] + red[row*4 + (wn^1)];
        rs[mi][half] = rsqrtf(tot*(1.f/64.f) + 1e-6f);
      }

    const int which = nt >> 3;
    const int head = (nt & 7)*2 + (wn >> 1);
    const int dbase = (wn & 1)*32;

    if (which == 2){
        #pragma unroll
        for (int mi=0;mi<4;mi++)
          #pragma unroll
          for (int half=0; half<2; ++half){
            int token = tok0 + wm*64 + mi*16 + half*8 + lg;
            int bb = token >> 11, ss = token & (NS-1);
            float rms = rs[mi][half];
            float* dst = g_V + ((size_t)((bb*NH + head)*NS + ss))*64 + dbase;
            #pragma unroll
            for (int ni=0;ni<4;ni++)
                *(float2*)(dst + ni*8 + 2*tg) =
                    make_float2(tf32r(c[mi][ni][half*2]*rms),
                                tf32r(c[mi][ni][half*2+1]*rms));
          }
    } else {
        const float* sc = (which==0)? qsc : ksc;
        float sc2[4][2];
        #pragma unroll
        for (int ni=0;ni<4;ni++){
            float2 s2 = *(const float2*)(sc + dbase + ni*8 + 2*tg);
            sc2[ni][0]=s2.x; sc2[ni][1]=s2.y;
        }
        uint4* gdst = (which==0)? g_Qp : g_Kp;
        #pragma unroll
        for (int mi=0;mi<4;mi++)
          #pragma unroll
          for (int half=0; half<2; ++half){
            int token = tok0 + wm*64 + mi*16 + half*8 + lg;
            int bb = token >> 11, ss = token & (NS-1);
            float rms = rs[mi][half];
            float vr[4][2];
            #pragma unroll
            for (int ni=0;ni<4;ni++){
                vr[ni][0] = c[mi][ni][half*2]*rms*sc2[ni][0];
                vr[ni][1] = c[mi][ni][half*2+1]*rms*sc2[ni][1];
            }
            const float* cb = cosp + (size_t)token*64 + dbase;
            const float* sb = sinp + (size_t)token*64 + dbase;
            float ov[4][2];
            #pragma unroll
            for (int ni=0;ni<4;ni++){
                float2 cv = *(const float2*)(cb + ni*8 + 2*tg);
                float2 sv = *(const float2*)(sb + ni*8 + 2*tg);
                int par = ni ^ 2;
                float r0 = (ni & 2) ? vr[par][0] : -vr[par][0];
                float r1 = (ni & 2) ? vr[par][1] : -vr[par][1];
                ov[ni][0] = vr[ni][0]*cv.x + r0*sv.x;
                ov[ni][1] = vr[ni][1]*cv.y + r1*sv.y;
            }
            uint4* dst = gdst + ((size_t)((bb*NH + head)*NS + ss))*16;
            #pragma unroll
            for (int cc=0; cc<2; ++cc){
                uint32_t h0,l0,h1,l1;
                bfsplit2(ov[2*cc][0],   ov[2*cc][1],   h0, l0);
                bfsplit2(ov[2*cc+1][0], ov[2*cc+1][1], h1, l1);
                dst[((wn&1)*2 + cc)*4 + tg] = make_uint4(h0, h1, l0, l1);
            }
          }
    }
}

// ---------------------------------------------------------------------------
// flash attention: 64 q rows/block, 4 warps, 3 CTAs/SM (69632B smem).
// (byte-identical to passing round-11 version)
// ---------------------------------------------------------------------------
#define AT_V   32768
#define AT_P   51200
#define ATTN_SMEM 69632

__global__ void __launch_bounds__(128, 3) attn_kernel()
{
    extern __shared__ __align__(16) char dsm[];
    float* Psf = (float*)(dsm + AT_P);             // [64][72]

    const int tid = threadIdx.x, lane = tid & 31, w = tid >> 5;
    const int lg = lane >> 2, tg = lane & 3;
    const int qt = blockIdx.x, h = blockIdx.y, b = blockIdx.z;
    const size_t bhrow = (size_t)(b*NH + h)*NS;
    const size_t bh64  = (size_t)(b*NH + h)*64;
    const uint32_t sdyn = smem_u32(dsm);

    // ---- stage Q into V region (swizzled 256B rows), extract frags ----
    {
        size_t qrow0 = bhrow + (size_t)qt*64;
        #pragma unroll
        for (int i=0;i<8;i++){
            int idx = i*128 + tid;
            int u = idx&3, cc = (idx>>2)&3, row = idx>>4;
            uint32_t ph = (uint32_t)((4*cc+u) ^ ((row&1)<<2));
            cpa16(sdyn + AT_V + row*256 + ph*16, g_Qp + (qrow0+row)*16 + cc*4 + u);
        }
        CP_COMMIT(); CP_WAIT(0);
        __syncthreads();
    }
    uint32_t qh[4][4], ql[4][4];
    #pragma unroll
    for (int cc=0; cc<4; ++cc){
        int r0 = w*16 + lg, r1 = r0 + 8;
        uint4 u0 = *(const uint4*)(dsm + AT_V + r0*256 + (((4*cc+tg)^((r0&1)<<2)))*16);
        uint4 u1 = *(const uint4*)(dsm + AT_V + r1*256 + (((4*cc+tg)^((r1&1)<<2)))*16);
        qh[cc][0]=u0.x; qh[cc][1]=u1.x; qh[cc][2]=u0.y; qh[cc][3]=u1.y;
        ql[cc][0]=u0.z; ql[cc][1]=u1.z; ql[cc][2]=u0.w; ql[cc][3]=u1.w;
    }
    __syncthreads();

    #define K_ISSUE(kt) do { \
        uint32_t kb = sdyn + ((kt)&1)*16384; \
        size_t krow0 = bhrow + (size_t)(kt)*64; \
        _Pragma("unroll") \
        for (int i=0;i<8;i++){ \
            int idx = i*128 + tid; \
            int u = idx&3, cc = (idx>>2)&3, row = idx>>4; \
            uint32_t ph = (uint32_t)((4*cc+u) ^ ((row&1)<<2)); \
            cpa16(kb + row*256 + ph*16, g_Kp + (krow0+row)*16 + cc*4 + u); \
        } \
        CP_COMMIT(); \
    } while(0)

    #define V_ISSUE(kt) do { \
        uint32_t vb = sdyn + AT_V; \
        _Pragma("unroll") \
        for (int i=0;i<8;i++){ \
            int idx = i*128 + tid; \
            int u16 = idx&15, row = idx>>4; \
            cpa16(vb + row*288 + u16*16, \
                  g_Vt + (bh64 + row)*1024 + (kt)*32 + u16*2); \
        } \
        CP_COMMIT(); \
    } while(0)

    float ofr[8][4];
    #pragma unroll
    for (int ni=0;ni<8;ni++){ ofr[ni][0]=0;ofr[ni][1]=0;ofr[ni][2]=0;ofr[ni][3]=0; }
    float m0=-INFINITY, m1=-INFINITY, l0=0.f, l1=0.f;
    const int prow = w*16 + lg;

    K_ISSUE(0);
    V_ISSUE(0);
    K_ISSUE(1);

    for (int kt=0; kt<NS/64; ++kt){
        if (kt == NS/64 - 1) CP_WAIT(0); else CP_WAIT(1);
        __syncthreads();
        const char* kb = dsm + (kt&1)*16384;
        const char* vb = dsm + AT_V;

        // ---- QK^T: bf16x2 3-term ----
        float sfr[8][4];
        #pragma unroll
        for (int ni=0;ni<8;ni++){ sfr[ni][0]=0;sfr[ni][1]=0;sfr[ni][2]=0;sfr[ni][3]=0; }
        #pragma unroll
        for (int ni=0;ni<8;ni++){
            int r = ni*8 + lg;
            #pragma unroll
            for (int cc=0; cc<4; ++cc){
                uint4 bu = *(const uint4*)(kb + r*256 + (((4*cc+tg)^((r&1)<<2)))*16);
                uint32_t bh[2] = {bu.x, bu.y};
                uint32_t bl[2] = {bu.z, bu.w};
                mmabf(sfr[ni], qh[cc], bh);
                mmabf(sfr[ni], qh[cc], bl);
                mmabf(sfr[ni], ql[cc], bh);
            }
        }
        // ---- online softmax ----
        float t0=-INFINITY, t1=-INFINITY;
        #pragma unroll
        for (int ni=0;ni<8;ni++){
            t0 = fmaxf(t0, fmaxf(sfr[ni][0], sfr[ni][1]));
            t1 = fmaxf(t1, fmaxf(sfr[ni][2], sfr[ni][3]));
        }
        t0 = fmaxf(t0, __shfl_xor_sync(0xffffffffu, t0, 1));
        t0 = fmaxf(t0, __shfl_xor_sync(0xffffffffu, t0, 2));
        t1 = fmaxf(t1, __shfl_xor_sync(0xffffffffu, t1, 1));
        t1 = fmaxf(t1, __shfl_xor_sync(0xffffffffu, t1, 2));
        float mn0 = fmaxf(m0, t0), mn1 = fmaxf(m1, t1);
        float a0 = __expf(m0 - mn0), a1 = __expf(m1 - mn1);
        float p0 = 0.f, p1 = 0.f;
        #pragma unroll
        for (int ni=0;ni<8;ni++){
            sfr[ni][0] = __expf(sfr[ni][0]-mn0); p0 += sfr[ni][0];
            sfr[ni][1] = __expf(sfr[ni][1]-mn0); p0 += sfr[ni][1];
            sfr[ni][2] = __expf(sfr[ni][2]-mn1); p1 += sfr[ni][2];
            sfr[ni][3] = __expf(sfr[ni][3]-mn1); p1 += sfr[ni][3];
        }
        p0 += __shfl_xor_sync(0xffffffffu, p0, 1);
        p0 += __shfl_xor_sync(0xffffffffu, p0, 2);
        p1 += __shfl_xor_sync(0xffffffffu, p1, 1);
        p1 += __shfl_xor_sync(0xffffffffu, p1, 2);
        l0 = l0*a0 + p0; l1 = l1*a1 + p1;
        m0 = mn0; m1 = mn1;
        // P (tf32) paired layout: logical col c -> slot ((c&3)<<1)|((c>>2)&1)
        {
            int c0 = 2*tg, c1 = 2*tg+1;
            int i0 = ((c0&3)<<1) | ((c0>>2)&1);
            int i1 = ((c1&3)<<1) | ((c1>>2)&1);
            #pragma unroll
            for (int ni=0;ni<8;ni++){
                ofr[ni][0]*=a0; ofr[ni][1]*=a0; ofr[ni][2]*=a1; ofr[ni][3]*=a1;
                Psf[prow*72     + ni*8 + i0] = tf32r(sfr[ni][0]);
                Psf[prow*72     + ni*8 + i1] = tf32r(sfr[ni][1]);
                Psf[(prow+8)*72 + ni*8 + i0] = tf32r(sfr[ni][2]);
                Psf[(prow+8)*72 + ni*8 + i1] = tf32r(sfr[ni][3]);
            }
        }
        __syncwarp();
        // ---- O += P * V (tf32, V^T paired: b-frag = 1 LDS.64) ----
        #pragma unroll
        for (int k2=0;k2<8;k2++){
            float2 f0 = *(const float2*)&Psf[prow*72     + k2*8 + tg*2];
            float2 f1 = *(const float2*)&Psf[(prow+8)*72 + k2*8 + tg*2];
            float pa[4] = {f0.x, f1.x, f0.y, f1.y};
            #pragma unroll
            for (int ni=0;ni<8;ni++){
                float2 bv2 = *(const float2*)(vb + (ni*8+lg)*288 + (k2*4+tg)*8);
                float bv[2] = {bv2.x, bv2.y};
                mma8(ofr[ni], pa, bv);
            }
        }
        __syncthreads();   // all warps done reading V(kt) and K(kt)
        if (kt + 1 < NS/64) V_ISSUE(kt+1);
        if (kt + 2 < NS/64) K_ISSUE(kt+2);
    }
    #undef K_ISSUE
    #undef V_ISSUE

    // ---- epilogue: write AO packed bf16 hi/lo ----
    float i0 = 1.f/l0, i1 = 1.f/l1;
    #pragma unroll
    for (int half=0; half<2; ++half){
        int token = b*NS + qt*64 + w*16 + half*8 + lg;
        float inv = half ? i1 : i0;
        float v[8][2];
        #pragma unroll
        for (int ni=0;ni<8;ni++){
            v[ni][0] = ofr[ni][half*2]*inv;
            v[ni][1] = ofr[ni][half*2+1]*inv;
        }
        uint4* dst = g_AOp + ((size_t)token*64 + h*4)*4;
        #pragma unroll
        for (int cc=0; cc<4; ++cc){
            uint32_t h0,l0w,h1,l1w;
            bfsplit2(v[2*cc][0],   v[2*cc][1],   h0, l0w);
            bfsplit2(v[2*cc+1][0], v[2*cc+1][1], h1, l1w);
            dst[cc*4 + tg] = make_uint4(h0, h1, l0w, l1w);
        }
    }
}

// ---------------------------------------------------------------------------
extern "C" void kernel_launch(void* const* d_in, const int* in_sizes, int n_in,
                              void* d_out, int out_size)
{
    (void)in_sizes; (void)n_in; (void)out_size;
    const float* X    = (const float*)d_in[0];
    const float* cosp = (const float*)d_in[1];
    const float* sinp = (const float*)d_in[2];
    // d_in[3] = position_ids (unused by reference)
    const float* wq   = (const float*)d_in[4];
    const float* wk   = (const float*)d_in[5];
    const float* wv   = (const float*)d_in[6];
    const float* wo   = (const float*)d_in[7];
    const float* qsc  = (const float*)d_in[8];
    const float* ksc  = (const float*)d_in[9];
    float* out = (float*)d_out;

    cudaFuncSetAttribute(gemm128,
                         cudaFuncAttributeMaxDynamicSharedMemorySize, GEMM_SMEM);
    cudaFuncSetAttribute(attn_kernel,
                         cudaFuncAttributeMaxDynamicSharedMemorySize, ATTN_SMEM);

    prep_x<<<NTOK*64/256, 256>>>(X);
    prep_w<<<4*ND*64/256, 256>>>(wq, wk, wv, wo);
    gemm128<<<dim3(NTOK/128, 24), 256, GEMM_SMEM>>>(0, cosp, sinp, qsc, ksc, nullptr);
    transp_v<<<dim3(NS/64, NH, NB), 128>>>();
    attn_kernel<<<dim3(NS/64, NH, NB), 128, ATTN_SMEM>>>();
    gemm128<<<dim3(NTOK/128, ND/128), 256, GEMM_SMEM>>>(1, nullptr, nullptr, nullptr, nullptr, out);
}

// round 15
// speedup vs baseline: 1.1766x; 1.1766x over previous
#include <cuda_runtime.h>
#include <cuda_bf16.h>
#include <math.h>
#include <stdint.h>

#define NB 4
#define NS 2048
#define ND 1024
#define NH 16
#define NHD 64
#define NTOK (NB*NS)

// ---------------- device global scratch (allocation-free) ----------------
// packed unit = 16B = {hi pair_t, hi pair_{t+4}, lo pair_t, lo pair_{t+4}}
__device__ uint4 g_Xp [(size_t)NTOK*64*4];        // X packed
__device__ uint4 g_Wp [(size_t)3*ND*64*4];        // wq|wk|wv packed
__device__ uint4 g_WOp[(size_t)ND*64*4];          // wo packed
__device__ uint4 g_Qp [(size_t)NB*NH*NS*16];      // Q packed
__device__ uint4 g_Kp [(size_t)NB*NH*NS*16];      // K packed
__device__ float g_V  [(size_t)NB*NH*NS*NHD];     // V fp32 (tf32-rounded), [bh][s][d]
__device__ float2 g_Vt[(size_t)NB*NH*64*1024];    // V^T paired: [bh][d][1024] pairs
__device__ uint4 g_AOp[(size_t)NTOK*64*4];        // attention out packed

// ---------------- helpers ----------------
__device__ __forceinline__ uint32_t smem_u32(const void* p){
    uint32_t a;
    asm("{ .reg .u64 t; cvta.to.shared.u64 t, %1; cvt.u32.u64 %0, t; }" : "=r"(a) : "l"(p));
    return a;
}
__device__ __forceinline__ float tf32r(float x){
    uint32_t y; asm("cvt.rna.tf32.f32 %0, %1;" : "=r"(y) : "f"(x));
    return __uint_as_float(y);
}
__device__ __forceinline__ void mma8(float c[4], const float a[4], const float b[2]){
    asm volatile(
      "mma.sync.aligned.m16n8k8.row.col.f32.tf32.tf32.f32 "
      "{%0,%1,%2,%3}, {%4,%5,%6,%7}, {%8,%9}, {%0,%1,%2,%3};\n"
      : "+f"(c[0]),"+f"(c[1]),"+f"(c[2]),"+f"(c[3])
      : "r"(__float_as_uint(a[0])),"r"(__float_as_uint(a[1])),
        "r"(__float_as_uint(a[2])),"r"(__float_as_uint(a[3])),
        "r"(__float_as_uint(b[0])),"r"(__float_as_uint(b[1])));
}
__device__ __forceinline__ void mmabf(float c[4], const uint32_t a[4], const uint32_t b[2]){
    asm volatile(
      "mma.sync.aligned.m16n8k16.row.col.f32.bf16.bf16.f32 "
      "{%0,%1,%2,%3}, {%4,%5,%6,%7}, {%8,%9}, {%0,%1,%2,%3};\n"
      : "+f"(c[0]),"+f"(c[1]),"+f"(c[2]),"+f"(c[3])
      : "r"(a[0]),"r"(a[1]),"r"(a[2]),"r"(a[3]), "r"(b[0]),"r"(b[1]));
}
__device__ __forceinline__ void cpa16(uint32_t saddr, const void* gaddr){
    asm volatile("cp.async.cg.shared.global [%0], [%1], 16;" :: "r"(saddr), "l"(gaddr) : "memory");
}
#define CP_COMMIT() asm volatile("cp.async.commit_group;" ::: "memory")
#define CP_WAIT(n)  asm volatile("cp.async.wait_group %0;" :: "n"(n) : "memory")

__device__ __forceinline__ uint32_t packbf2(__nv_bfloat16 a, __nv_bfloat16 b){
    return (uint32_t)__bfloat16_as_ushort(a) | ((uint32_t)__bfloat16_as_ushort(b) << 16);
}
__device__ __forceinline__ void bfsplit2(float a, float b, uint32_t& hi, uint32_t& lo){
    __nv_bfloat16 ha = __float2bfloat16(a), hb = __float2bfloat16(b);
    hi = packbf2(ha, hb);
    lo = packbf2(__float2bfloat16(a - __bfloat162float(ha)),
                 __float2bfloat16(b - __bfloat162float(hb)));
}

// ---------------------------------------------------------------------------
// prep: one thread packs one k16 chunk
// ---------------------------------------------------------------------------
__device__ __forceinline__ void pack_chunk(const float* src, uint4* dst){
    float x[16];
    #pragma unroll
    for (int i=0;i<4;i++){ float4 v = *(const float4*)(src + i*4);
        x[i*4]=v.x; x[i*4+1]=v.y; x[i*4+2]=v.z; x[i*4+3]=v.w; }
    uint32_t hi[8], lo[8];
    #pragma unroll
    for (int j=0;j<8;j++) bfsplit2(x[2*j], x[2*j+1], hi[j], lo[j]);
    #pragma unroll
    for (int u=0;u<4;u++) dst[u] = make_uint4(hi[u], hi[u+4], lo[u], lo[u+4]);
}

__global__ __launch_bounds__(256) void prep_x(const float* __restrict__ X){
    int i = blockIdx.x*256 + threadIdx.x;
    pack_chunk(X + (size_t)i*16, g_Xp + (size_t)i*4);
}

__global__ __launch_bounds__(256) void prep_w(
    const float* __restrict__ wq, const float* __restrict__ wk,
    const float* __restrict__ wv, const float* __restrict__ wo){
    int i = blockIdx.x*256 + threadIdx.x;
    if (i < 3*ND*64){
        int row = i >> 6, c = i & 63;
        int which = row >> 10, r = row & 1023;
        const float* src = (which==0)? wq : (which==1)? wk : wv;
        pack_chunk(src + (size_t)r*ND + c*16, g_Wp + (size_t)i*4);
    } else {
        int j = i - 3*ND*64;
        int row = j >> 6, c = j & 63;
        pack_chunk(wo + (size_t)row*ND + c*16, g_WOp + (size_t)j*4);
    }
}

// ---------------------------------------------------------------------------
// V transpose: g_V [bh][s][d] -> g_Vt [bh][d] paired along s.
// ---------------------------------------------------------------------------
__global__ __launch_bounds__(128) void transp_v(){
    __shared__ float Vs[64*65];
    const int tid = threadIdx.x;
    const int t3 = blockIdx.x, h = blockIdx.y, b = blockIdx.z;
    const size_t bh = (size_t)(b*NH + h);
    const float* src = g_V + (bh*NS + (size_t)t3*64)*64;
    #pragma unroll
    for (int i=0;i<8;i++){
        int idx = i*128 + tid, row = idx>>4, c4 = idx&15;
        float4 v = *(const float4*)(src + row*64 + c4*4);
        Vs[row*65 + c4*4+0]=v.x; Vs[row*65 + c4*4+1]=v.y;
        Vs[row*65 + c4*4+2]=v.z; Vs[row*65 + c4*4+3]=v.w;
    }
    __syncthreads();
    float2* dst = g_Vt + bh*64*1024;
    #pragma unroll
    for (int i=0;i<16;i++){
        int idx = i*128 + tid;
        int t = idx&3, jl = (idx>>2)&7, d = idx>>5;
        int s = jl*8 + t;
        dst[(size_t)d*1024 + (t3*8 + jl)*4 + t] =
            make_float2(Vs[s*65 + d], Vs[(s+4)*65 + d]);
    }
}

// ---------------------------------------------------------------------------
// GEMM: C[128x128] = A[128x1024] * B[128x1024]^T, bf16x2 3-term.
// 8 warps (256 thr), warp tile 64x32, k-tile=32 (2 chunks / iter, 32 iters).
// 3-stage cp.async pipeline, XOR-swizzled 128B rows (no padding):
//   unit' = u ^ ((row&1)<<2); stage = 32768B (A 16384 + B 16384).
// Issue runs 2 iterations ahead; ONE barrier per iteration.
// mode 0: RMS(+scale)+RoPE epilogue (cross-warp RMS via smem red buffer)
// mode 1: plain store
// ---------------------------------------------------------------------------
#define GSTAGE 32768
#define GEMM_SMEM (3*GSTAGE)

__global__ void __launch_bounds__(256, 2) gemm128(
    int mode,
    const float* __restrict__ cosp, const float* __restrict__ sinp,
    const float* __restrict__ qsc,  const float* __restrict__ ksc,
    float* __restrict__ outp)
{
    extern __shared__ __align__(16) char dsm[];
    const int tid = threadIdx.x, lane = tid & 31, w = tid >> 5;
    const int lg = lane >> 2, tg = lane & 3;
    const int wm = w >> 2, wn = w & 3;
    const int tok0 = blockIdx.x * 128;
    const int nt = blockIdx.y;
    const int brow0 = nt * 128;
    const uint32_t sdyn = smem_u32(dsm);

    const uint4* Aunits = mode ? g_AOp : g_Xp;
    const uint4* Bunits = mode ? g_WOp : g_Wp;

    float c[4][4][4];
    #pragma unroll
    for (int mi=0;mi<4;mi++)
      #pragma unroll
      for (int ni=0;ni<4;ni++)
        #pragma unroll
        for (int q=0;q<4;q++) c[mi][ni][q]=0.f;

    // issue one k32 tile (2 chunks) into stage (ck % 3)
    #define G_ISSUE(ck) do { \
        uint32_t sa = sdyn + ((ck)%3)*GSTAGE; \
        uint32_t sb = sa + 16384; \
        int ck2 = (ck)*2; \
        _Pragma("unroll") \
        for (int i=0;i<4;i++){ \
            int idx = i*256 + tid; \
            int u = idx&7, row = idx>>3; \
            uint32_t ph = (uint32_t)(u ^ ((row&1)<<2)); \
            int chk = ck2 + (u>>2), ui = u&3; \
            cpa16(sa + row*128 + ph*16, \
                  Aunits + ((size_t)(tok0+row)*64 + chk)*4 + ui); \
            cpa16(sb + row*128 + ph*16, \
                  Bunits + ((size_t)(brow0+row)*64 + chk)*4 + ui); \
        } \
        CP_COMMIT(); \
    } while(0)

    G_ISSUE(0); G_ISSUE(1);
    for (int ck = 0; ck < 32; ++ck){
        if (ck < 31) CP_WAIT(1); else CP_WAIT(0);
        __syncthreads();
        if (ck + 2 < 32) G_ISSUE(ck+2);

        const char* pA = dsm + (ck%3)*GSTAGE;
        const char* pB = pA + 16384;
        #pragma unroll
        for (int ch=0; ch<2; ++ch){
            uint32_t ah[4][4], al[4][4];
            #pragma unroll
            for (int mi=0;mi<4;mi++){
                int r0 = wm*64 + mi*16 + lg, r1 = r0 + 8;
                uint4 u0 = *(const uint4*)(pA + r0*128 + (((4*ch+tg)^((r0&1)<<2)))*16);
                uint4 u1 = *(const uint4*)(pA + r1*128 + (((4*ch+tg)^((r1&1)<<2)))*16);
                ah[mi][0]=u0.x; ah[mi][1]=u1.x; ah[mi][2]=u0.y; ah[mi][3]=u1.y;
                al[mi][0]=u0.z; al[mi][1]=u1.z; al[mi][2]=u0.w; al[mi][3]=u1.w;
            }
            #pragma unroll
            for (int ni=0;ni<4;ni++){
                int r = wn*32 + ni*8 + lg;
                uint4 bu = *(const uint4*)(pB + r*128 + (((4*ch+tg)^((r&1)<<2)))*16);
                uint32_t bh[2] = {bu.x, bu.y};
                uint32_t bl[2] = {bu.z, bu.w};
                #pragma unroll
                for (int mi=0;mi<4;mi++){
                    mmabf(c[mi][ni], ah[mi], bh);
                    mmabf(c[mi][ni], ah[mi], bl);
                    mmabf(c[mi][ni], al[mi], bh);
                }
            }
        }
    }
    #undef G_ISSUE

    if (mode == 1){
        #pragma unroll
        for (int mi=0;mi<4;mi++)
          #pragma unroll
          for (int half=0; half<2; ++half){
            int token = tok0 + wm*64 + mi*16 + half*8 + lg;
            float* dst = outp + (size_t)token*ND + nt*128 + wn*32;
            #pragma unroll
            for (int ni=0;ni<4;ni++)
                *(float2*)(dst + ni*8 + 2*tg) =
                    make_float2(c[mi][ni][half*2], c[mi][ni][half*2+1]);
          }
        return;
    }

    // ---- mode 0: cross-warp RMS (warp wn pairs with wn^1 over the same head) ----
    __syncthreads();
    float* red = (float*)dsm;              // [128][4]
    float part[4][2];
    #pragma unroll
    for (int mi=0;mi<4;mi++){
        float s0=0.f, s1=0.f;
        #pragma unroll
        for (int ni=0;ni<4;ni++){
            s0 += c[mi][ni][0]*c[mi][ni][0] + c[mi][ni][1]*c[mi][ni][1];
            s1 += c[mi][ni][2]*c[mi][ni][2] + c[mi][ni][3]*c[mi][ni][3];
        }
        s0 += __shfl_xor_sync(0xffffffffu, s0, 1);
        s0 += __shfl_xor_sync(0xffffffffu, s0, 2);
        s1 += __shfl_xor_sync(0xffffffffu, s1, 1);
        s1 += __shfl_xor_sync(0xffffffffu, s1, 2);
        part[mi][0]=s0; part[mi][1]=s1;
        if (tg == 0){
            red[(wm*64 + mi*16 + lg)*4 + wn]     = s0;
            red[(wm*64 + mi*16 + 8 + lg)*4 + wn] = s1;
        }
    }
    __syncthreads();
    float rs[4][2];
    #pragma unroll
    for (int mi=0;mi<4;mi++)
      #pragma unroll
      for (int half=0; half<2; ++half){
        int row = wm*64 + mi*16 + half*8 + lg;
        float tot = part[mi][half] + red[row*4 + (wn^1)];
        rs[mi][half] = rsqrtf(tot*(1.f/64.f) + 1e-6f);
      }

    const int which = nt >> 3;
    const int head = (nt & 7)*2 + (wn >> 1);
    const int dbase = (wn & 1)*32;

    if (which == 2){
        #pragma unroll
        for (int mi=0;mi<4;mi++)
          #pragma unroll
          for (int half=0; half<2; ++half){
            int token = tok0 + wm*64 + mi*16 + half*8 + lg;
            int bb = token >> 11, ss = token & (NS-1);
            float rms = rs[mi][half];
            float* dst = g_V + ((size_t)((bb*NH + head)*NS + ss))*64 + dbase;
            #pragma unroll
            for (int ni=0;ni<4;ni++)
                *(float2*)(dst + ni*8 + 2*tg) =
                    make_float2(tf32r(c[mi][ni][half*2]*rms),
                                tf32r(c[mi][ni][half*2+1]*rms));
          }
    } else {
        const float* sc = (which==0)? qsc : ksc;
        float sc2[4][2];
        #pragma unroll
        for (int ni=0;ni<4;ni++){
            float2 s2 = *(const float2*)(sc + dbase + ni*8 + 2*tg);
            sc2[ni][0]=s2.x; sc2[ni][1]=s2.y;
        }
        uint4* gdst = (which==0)? g_Qp : g_Kp;
        #pragma unroll
        for (int mi=0;mi<4;mi++)
          #pragma unroll
          for (int half=0; half<2; ++half){
            int token = tok0 + wm*64 + mi*16 + half*8 + lg;
            int bb = token >> 11, ss = token & (NS-1);
            float rms = rs[mi][half];
            float vr[4][2];
            #pragma unroll
            for (int ni=0;ni<4;ni++){
                vr[ni][0] = c[mi][ni][half*2]*rms*sc2[ni][0];
                vr[ni][1] = c[mi][ni][half*2+1]*rms*sc2[ni][1];
            }
            const float* cb = cosp + (size_t)token*64 + dbase;
            const float* sb = sinp + (size_t)token*64 + dbase;
            float ov[4][2];
            #pragma unroll
            for (int ni=0;ni<4;ni++){
                float2 cv = *(const float2*)(cb + ni*8 + 2*tg);
                float2 sv = *(const float2*)(sb + ni*8 + 2*tg);
                int par = ni ^ 2;
                float r0 = (ni & 2) ? vr[par][0] : -vr[par][0];
                float r1 = (ni & 2) ? vr[par][1] : -vr[par][1];
                ov[ni][0] = vr[ni][0]*cv.x + r0*sv.x;
                ov[ni][1] = vr[ni][1]*cv.y + r1*sv.y;
            }
            uint4* dst = gdst + ((size_t)((bb*NH + head)*NS + ss))*16;
            #pragma unroll
            for (int cc=0; cc<2; ++cc){
                uint32_t h0,l0,h1,l1;
                bfsplit2(ov[2*cc][0],   ov[2*cc][1],   h0, l0);
                bfsplit2(ov[2*cc+1][0], ov[2*cc+1][1], h1, l1);
                dst[((wn&1)*2 + cc)*4 + tg] = make_uint4(h0, h1, l0, l1);
            }
          }
    }
}

// ---------------------------------------------------------------------------
// flash attention: 64 q rows/block, 4 warps, 3 CTAs/SM (69632B smem).
// (byte-identical to passing round-11 version)
// ---------------------------------------------------------------------------
#define AT_V   32768
#define AT_P   51200
#define ATTN_SMEM 69632

__global__ void __launch_bounds__(128, 3) attn_kernel()
{
    extern __shared__ __align__(16) char dsm[];
    float* Psf = (float*)(dsm + AT_P);             // [64][72]

    const int tid = threadIdx.x, lane = tid & 31, w = tid >> 5;
    const int lg = lane >> 2, tg = lane & 3;
    const int qt = blockIdx.x, h = blockIdx.y, b = blockIdx.z;
    const size_t bhrow = (size_t)(b*NH + h)*NS;
    const size_t bh64  = (size_t)(b*NH + h)*64;
    const uint32_t sdyn = smem_u32(dsm);

    // ---- stage Q into V region (swizzled 256B rows), extract frags ----
    {
        size_t qrow0 = bhrow + (size_t)qt*64;
        #pragma unroll
        for (int i=0;i<8;i++){
            int idx = i*128 + tid;
            int u = idx&3, cc = (idx>>2)&3, row = idx>>4;
            uint32_t ph = (uint32_t)((4*cc+u) ^ ((row&1)<<2));
            cpa16(sdyn + AT_V + row*256 + ph*16, g_Qp + (qrow0+row)*16 + cc*4 + u);
        }
        CP_COMMIT(); CP_WAIT(0);
        __syncthreads();
    }
    uint32_t qh[4][4], ql[4][4];
    #pragma unroll
    for (int cc=0; cc<4; ++cc){
        int r0 = w*16 + lg, r1 = r0 + 8;
        uint4 u0 = *(const uint4*)(dsm + AT_V + r0*256 + (((4*cc+tg)^((r0&1)<<2)))*16);
        uint4 u1 = *(const uint4*)(dsm + AT_V + r1*256 + (((4*cc+tg)^((r1&1)<<2)))*16);
        qh[cc][0]=u0.x; qh[cc][1]=u1.x; qh[cc][2]=u0.y; qh[cc][3]=u1.y;
        ql[cc][0]=u0.z; ql[cc][1]=u1.z; ql[cc][2]=u0.w; ql[cc][3]=u1.w;
    }
    __syncthreads();

    #define K_ISSUE(kt) do { \
        uint32_t kb = sdyn + ((kt)&1)*16384; \
        size_t krow0 = bhrow + (size_t)(kt)*64; \
        _Pragma("unroll") \
        for (int i=0;i<8;i++){ \
            int idx = i*128 + tid; \
            int u = idx&3, cc = (idx>>2)&3, row = idx>>4; \
            uint32_t ph = (uint32_t)((4*cc+u) ^ ((row&1)<<2)); \
            cpa16(kb + row*256 + ph*16, g_Kp + (krow0+row)*16 + cc*4 + u); \
        } \
        CP_COMMIT(); \
    } while(0)

    #define V_ISSUE(kt) do { \
        uint32_t vb = sdyn + AT_V; \
        _Pragma("unroll") \
        for (int i=0;i<8;i++){ \
            int idx = i*128 + tid; \
            int u16 = idx&15, row = idx>>4; \
            cpa16(vb + row*288 + u16*16, \
                  g_Vt + (bh64 + row)*1024 + (kt)*32 + u16*2); \
        } \
        CP_COMMIT(); \
    } while(0)

    float ofr[8][4];
    #pragma unroll
    for (int ni=0;ni<8;ni++){ ofr[ni][0]=0;ofr[ni][1]=0;ofr[ni][2]=0;ofr[ni][3]=0; }
    float m0=-INFINITY, m1=-INFINITY, l0=0.f, l1=0.f;
    const int prow = w*16 + lg;

    K_ISSUE(0);
    V_ISSUE(0);
    K_ISSUE(1);

    for (int kt=0; kt<NS/64; ++kt){
        if (kt == NS/64 - 1) CP_WAIT(0); else CP_WAIT(1);
        __syncthreads();
        const char* kb = dsm + (kt&1)*16384;
        const char* vb = dsm + AT_V;

        // ---- QK^T: bf16x2 3-term ----
        float sfr[8][4];
        #pragma unroll
        for (int ni=0;ni<8;ni++){ sfr[ni][0]=0;sfr[ni][1]=0;sfr[ni][2]=0;sfr[ni][3]=0; }
        #pragma unroll
        for (int ni=0;ni<8;ni++){
            int r = ni*8 + lg;
            #pragma unroll
            for (int cc=0; cc<4; ++cc){
                uint4 bu = *(const uint4*)(kb + r*256 + (((4*cc+tg)^((r&1)<<2)))*16);
                uint32_t bh[2] = {bu.x, bu.y};
                uint32_t bl[2] = {bu.z, bu.w};
                mmabf(sfr[ni], qh[cc], bh);
                mmabf(sfr[ni], qh[cc], bl);
                mmabf(sfr[ni], ql[cc], bh);
            }
        }
        // ---- online softmax ----
        float t0=-INFINITY, t1=-INFINITY;
        #pragma unroll
        for (int ni=0;ni<8;ni++){
            t0 = fmaxf(t0, fmaxf(sfr[ni][0], sfr[ni][1]));
            t1 = fmaxf(t1, fmaxf(sfr[ni][2], sfr[ni][3]));
        }
        t0 = fmaxf(t0, __shfl_xor_sync(0xffffffffu, t0, 1));
        t0 = fmaxf(t0, __shfl_xor_sync(0xffffffffu, t0, 2));
        t1 = fmaxf(t1, __shfl_xor_sync(0xffffffffu, t1, 1));
        t1 = fmaxf(t1, __shfl_xor_sync(0xffffffffu, t1, 2));
        float mn0 = fmaxf(m0, t0), mn1 = fmaxf(m1, t1);
        float a0 = __expf(m0 - mn0), a1 = __expf(m1 - mn1);
        float p0 = 0.f, p1 = 0.f;
        #pragma unroll
        for (int ni=0;ni<8;ni++){
            sfr[ni][0] = __expf(sfr[ni][0]-mn0); p0 += sfr[ni][0];
            sfr[ni][1] = __expf(sfr[ni][1]-mn0); p0 += sfr[ni][1];
            sfr[ni][2] = __expf(sfr[ni][2]-mn1); p1 += sfr[ni][2];
            sfr[ni][3] = __expf(sfr[ni][3]-mn1); p1 += sfr[ni][3];
        }
        p0 += __shfl_xor_sync(0xffffffffu, p0, 1);
        p0 += __shfl_xor_sync(0xffffffffu, p0, 2);
        p1 += __shfl_xor_sync(0xffffffffu, p1, 1);
        p1 += __shfl_xor_sync(0xffffffffu, p1, 2);
        l0 = l0*a0 + p0; l1 = l1*a1 + p1;
        m0 = mn0; m1 = mn1;
        // P (tf32) paired layout: logical col c -> slot ((c&3)<<1)|((c>>2)&1)
        {
            int c0 = 2*tg, c1 = 2*tg+1;
            int i0 = ((c0&3)<<1) | ((c0>>2)&1);
            int i1 = ((c1&3)<<1) | ((c1>>2)&1);
            #pragma unroll
            for (int ni=0;ni<8;ni++){
                ofr[ni][0]*=a0; ofr[ni][1]*=a0; ofr[ni][2]*=a1; ofr[ni][3]*=a1;
                Psf[prow*72     + ni*8 + i0] = tf32r(sfr[ni][0]);
                Psf[prow*72     + ni*8 + i1] = tf32r(sfr[ni][1]);
                Psf[(prow+8)*72 + ni*8 + i0] = tf32r(sfr[ni][2]);
                Psf[(prow+8)*72 + ni*8 + i1] = tf32r(sfr[ni][3]);
            }
        }
        __syncwarp();
        // ---- O += P * V (tf32, V^T paired: b-frag = 1 LDS.64) ----
        #pragma unroll
        for (int k2=0;k2<8;k2++){
            float2 f0 = *(const float2*)&Psf[prow*72     + k2*8 + tg*2];
            float2 f1 = *(const float2*)&Psf[(prow+8)*72 + k2*8 + tg*2];
            float pa[4] = {f0.x, f1.x, f0.y, f1.y};
            #pragma unroll
            for (int ni=0;ni<8;ni++){
                float2 bv2 = *(const float2*)(vb + (ni*8+lg)*288 + (k2*4+tg)*8);
                float bv[2] = {bv2.x, bv2.y};
                mma8(ofr[ni], pa, bv);
            }
        }
        __syncthreads();   // all warps done reading V(kt) and K(kt)
        if (kt + 1 < NS/64) V_ISSUE(kt+1);
        if (kt + 2 < NS/64) K_ISSUE(kt+2);
    }
    #undef K_ISSUE
    #undef V_ISSUE

    // ---- epilogue: write AO packed bf16 hi/lo ----
    float i0 = 1.f/l0, i1 = 1.f/l1;
    #pragma unroll
    for (int half=0; half<2; ++half){
        int token = b*NS + qt*64 + w*16 + half*8 + lg;
        float inv = half ? i1 : i0;
        float v[8][2];
        #pragma unroll
        for (int ni=0;ni<8;ni++){
            v[ni][0] = ofr[ni][half*2]*inv;
            v[ni][1] = ofr[ni][half*2+1]*inv;
        }
        uint4* dst = g_AOp + ((size_t)token*64 + h*4)*4;
        #pragma unroll
        for (int cc=0; cc<4; ++cc){
            uint32_t h0,l0w,h1,l1w;
            bfsplit2(v[2*cc][0],   v[2*cc][1],   h0, l0w);
            bfsplit2(v[2*cc+1][0], v[2*cc+1][1], h1, l1w);
            dst[cc*4 + tg] = make_uint4(h0, h1, l0w, l1w);
        }
    }
}

// ---------------------------------------------------------------------------
extern "C" void kernel_launch(void* const* d_in, const int* in_sizes, int n_in,
                              void* d_out, int out_size)
{
    (void)in_sizes; (void)n_in; (void)out_size;
    const float* X    = (const float*)d_in[0];
    const float* cosp = (const float*)d_in[1];
    const float* sinp = (const float*)d_in[2];
    // d_in[3] = position_ids (unused by reference)
    const float* wq   = (const float*)d_in[4];
    const float* wk   = (const float*)d_in[5];
    const float* wv   = (const float*)d_in[6];
    const float* wo   = (const float*)d_in[7];
    const float* qsc  = (const float*)d_in[8];
    const float* ksc  = (const float*)d_in[9];
    float* out = (float*)d_out;

    cudaFuncSetAttribute(gemm128,
                         cudaFuncAttributeMaxDynamicSharedMemorySize, GEMM_SMEM);
    cudaFuncSetAttribute(attn_kernel,
                         cudaFuncAttributeMaxDynamicSharedMemorySize, ATTN_SMEM);

    prep_x<<<NTOK*64/256, 256>>>(X);
    prep_w<<<4*ND*64/256, 256>>>(wq, wk, wv, wo);
    gemm128<<<dim3(NTOK/128, 24), 256, GEMM_SMEM>>>(0, cosp, sinp, qsc, ksc, nullptr);
    transp_v<<<dim3(NS/64, NH, NB), 128>>>();
    attn_kernel<<<dim3(NS/64, NH, NB), 128, ATTN_SMEM>>>();
    gemm128<<<dim3(NTOK/128, ND/128), 256, GEMM_SMEM>>>(1, nullptr, nullptr, nullptr, nullptr, out);
}

// round 16
// speedup vs baseline: 1.2366x; 1.0510x over previous
#include <cuda_runtime.h>
#include <cuda_bf16.h>
#include <math.h>
#include <stdint.h>

#define NB 4
#define NS 2048
#define ND 1024
#define NH 16
#define NHD 64
#define NTOK (NB*NS)

// ---------------- device global scratch (allocation-free) ----------------
// packed unit = 16B = {hi pair_t, hi pair_{t+4}, lo pair_t, lo pair_{t+4}}
__device__ uint4 g_Xp [(size_t)NTOK*64*4];        // X packed
__device__ uint4 g_Wp [(size_t)3*ND*64*4];        // wq|wk|wv packed
__device__ uint4 g_WOp[(size_t)ND*64*4];          // wo packed
__device__ uint4 g_Qp [(size_t)NB*NH*NS*16];      // Q packed
__device__ uint4 g_Kp [(size_t)NB*NH*NS*16];      // K packed
__device__ float g_V  [(size_t)NB*NH*NS*NHD];     // V fp32, [bh][s][d]
__device__ float2 g_Vt[(size_t)NB*NH*64*1024];    // V^T adjacent-paired: [bh][d][1024]
__device__ uint4 g_AOp[(size_t)NTOK*64*4];        // attention out packed

// ---------------- helpers ----------------
__device__ __forceinline__ uint32_t smem_u32(const void* p){
    uint32_t a;
    asm("{ .reg .u64 t; cvta.to.shared.u64 t, %1; cvt.u32.u64 %0, t; }" : "=r"(a) : "l"(p));
    return a;
}
__device__ __forceinline__ float tf32r(float x){
    uint32_t y; asm("cvt.rna.tf32.f32 %0, %1;" : "=r"(y) : "f"(x));
    return __uint_as_float(y);
}
__device__ __forceinline__ void mma8(float c[4], const float a[4], const float b[2]){
    asm volatile(
      "mma.sync.aligned.m16n8k8.row.col.f32.tf32.tf32.f32 "
      "{%0,%1,%2,%3}, {%4,%5,%6,%7}, {%8,%9}, {%0,%1,%2,%3};\n"
      : "+f"(c[0]),"+f"(c[1]),"+f"(c[2]),"+f"(c[3])
      : "r"(__float_as_uint(a[0])),"r"(__float_as_uint(a[1])),
        "r"(__float_as_uint(a[2])),"r"(__float_as_uint(a[3])),
        "r"(__float_as_uint(b[0])),"r"(__float_as_uint(b[1])));
}
__device__ __forceinline__ void mmabf(float c[4], const uint32_t a[4], const uint32_t b[2]){
    asm volatile(
      "mma.sync.aligned.m16n8k16.row.col.f32.bf16.bf16.f32 "
      "{%0,%1,%2,%3}, {%4,%5,%6,%7}, {%8,%9}, {%0,%1,%2,%3};\n"
      : "+f"(c[0]),"+f"(c[1]),"+f"(c[2]),"+f"(c[3])
      : "r"(a[0]),"r"(a[1]),"r"(a[2]),"r"(a[3]), "r"(b[0]),"r"(b[1]));
}
__device__ __forceinline__ void cpa16(uint32_t saddr, const void* gaddr){
    asm volatile("cp.async.cg.shared.global [%0], [%1], 16;" :: "r"(saddr), "l"(gaddr) : "memory");
}
#define CP_COMMIT() asm volatile("cp.async.commit_group;" ::: "memory")
#define CP_WAIT(n)  asm volatile("cp.async.wait_group %0;" :: "n"(n) : "memory")

__device__ __forceinline__ uint32_t packbf2(__nv_bfloat16 a, __nv_bfloat16 b){
    return (uint32_t)__bfloat16_as_ushort(a) | ((uint32_t)__bfloat16_as_ushort(b) << 16);
}
__device__ __forceinline__ void bfsplit2(float a, float b, uint32_t& hi, uint32_t& lo){
    __nv_bfloat16 ha = __float2bfloat16(a), hb = __float2bfloat16(b);
    hi = packbf2(ha, hb);
    lo = packbf2(__float2bfloat16(a - __bfloat162float(ha)),
                 __float2bfloat16(b - __bfloat162float(hb)));
}

// ---------------------------------------------------------------------------
// prep: one thread packs one k16 chunk
// ---------------------------------------------------------------------------
__device__ __forceinline__ void pack_chunk(const float* src, uint4* dst){
    float x[16];
    #pragma unroll
    for (int i=0;i<4;i++){ float4 v = *(const float4*)(src + i*4);
        x[i*4]=v.x; x[i*4+1]=v.y; x[i*4+2]=v.z; x[i*4+3]=v.w; }
    uint32_t hi[8], lo[8];
    #pragma unroll
    for (int j=0;j<8;j++) bfsplit2(x[2*j], x[2*j+1], hi[j], lo[j]);
    #pragma unroll
    for (int u=0;u<4;u++) dst[u] = make_uint4(hi[u], hi[u+4], lo[u], lo[u+4]);
}

__global__ __launch_bounds__(256) void prep_x(const float* __restrict__ X){
    int i = blockIdx.x*256 + threadIdx.x;
    pack_chunk(X + (size_t)i*16, g_Xp + (size_t)i*4);
}

__global__ __launch_bounds__(256) void prep_w(
    const float* __restrict__ wq, const float* __restrict__ wk,
    const float* __restrict__ wv, const float* __restrict__ wo){
    int i = blockIdx.x*256 + threadIdx.x;
    if (i < 3*ND*64){
        int row = i >> 6, c = i & 63;
        int which = row >> 10, r = row & 1023;
        const float* src = (which==0)? wq : (which==1)? wk : wv;
        pack_chunk(src + (size_t)r*ND + c*16, g_Wp + (size_t)i*4);
    } else {
        int j = i - 3*ND*64;
        int row = j >> 6, c = j & 63;
        pack_chunk(wo + (size_t)row*ND + c*16, g_WOp + (size_t)j*4);
    }
}

// ---------------------------------------------------------------------------
// V transpose: g_V [bh][s][d] -> g_Vt [bh][d] with ADJACENT pairing:
// pair (t3*8+jl)*4+t = {V[t3*64 + jl*8 + 2t][d], V[t3*64 + jl*8 + 2t+1][d]}
// ---------------------------------------------------------------------------
__global__ __launch_bounds__(128) void transp_v(){
    __shared__ float Vs[64*65];
    const int tid = threadIdx.x;
    const int t3 = blockIdx.x, h = blockIdx.y, b = blockIdx.z;
    const size_t bh = (size_t)(b*NH + h);
    const float* src = g_V + (bh*NS + (size_t)t3*64)*64;
    #pragma unroll
    for (int i=0;i<8;i++){
        int idx = i*128 + tid, row = idx>>4, c4 = idx&15;
        float4 v = *(const float4*)(src + row*64 + c4*4);
        Vs[row*65 + c4*4+0]=v.x; Vs[row*65 + c4*4+1]=v.y;
        Vs[row*65 + c4*4+2]=v.z; Vs[row*65 + c4*4+3]=v.w;
    }
    __syncthreads();
    float2* dst = g_Vt + bh*64*1024;
    #pragma unroll
    for (int i=0;i<16;i++){
        int idx = i*128 + tid;
        int t = idx&3, jl = (idx>>2)&7, d = idx>>5;
        int s = jl*8 + 2*t;
        dst[(size_t)d*1024 + (t3*8 + jl)*4 + t] =
            make_float2(Vs[s*65 + d], Vs[(s+1)*65 + d]);
    }
}

// ---------------------------------------------------------------------------
// GEMM: identical to round-15 passing version (3-stage, XOR swizzle, 16 warps)
// ---------------------------------------------------------------------------
#define GSTAGE 32768
#define GEMM_SMEM (3*GSTAGE)

__global__ void __launch_bounds__(256, 2) gemm128(
    int mode,
    const float* __restrict__ cosp, const float* __restrict__ sinp,
    const float* __restrict__ qsc,  const float* __restrict__ ksc,
    float* __restrict__ outp)
{
    extern __shared__ __align__(16) char dsm[];
    const int tid = threadIdx.x, lane = tid & 31, w = tid >> 5;
    const int lg = lane >> 2, tg = lane & 3;
    const int wm = w >> 2, wn = w & 3;
    const int tok0 = blockIdx.x * 128;
    const int nt = blockIdx.y;
    const int brow0 = nt * 128;
    const uint32_t sdyn = smem_u32(dsm);

    const uint4* Aunits = mode ? g_AOp : g_Xp;
    const uint4* Bunits = mode ? g_WOp : g_Wp;

    float c[4][4][4];
    #pragma unroll
    for (int mi=0;mi<4;mi++)
      #pragma unroll
      for (int ni=0;ni<4;ni++)
        #pragma unroll
        for (int q=0;q<4;q++) c[mi][ni][q]=0.f;

    #define G_ISSUE(ck) do { \
        uint32_t sa = sdyn + ((ck)%3)*GSTAGE; \
        uint32_t sb = sa + 16384; \
        int ck2 = (ck)*2; \
        _Pragma("unroll") \
        for (int i=0;i<4;i++){ \
            int idx = i*256 + tid; \
            int u = idx&7, row = idx>>3; \
            uint32_t ph = (uint32_t)(u ^ ((row&1)<<2)); \
            int chk = ck2 + (u>>2), ui = u&3; \
            cpa16(sa + row*128 + ph*16, \
                  Aunits + ((size_t)(tok0+row)*64 + chk)*4 + ui); \
            cpa16(sb + row*128 + ph*16, \
                  Bunits + ((size_t)(brow0+row)*64 + chk)*4 + ui); \
        } \
        CP_COMMIT(); \
    } while(0)

    G_ISSUE(0); G_ISSUE(1);
    for (int ck = 0; ck < 32; ++ck){
        if (ck < 31) CP_WAIT(1); else CP_WAIT(0);
        __syncthreads();
        if (ck + 2 < 32) G_ISSUE(ck+2);

        const char* pA = dsm + (ck%3)*GSTAGE;
        const char* pB = pA + 16384;
        #pragma unroll
        for (int ch=0; ch<2; ++ch){
            uint32_t ah[4][4], al[4][4];
            #pragma unroll
            for (int mi=0;mi<4;mi++){
                int r0 = wm*64 + mi*16 + lg, r1 = r0 + 8;
                uint4 u0 = *(const uint4*)(pA + r0*128 + (((4*ch+tg)^((r0&1)<<2)))*16);
                uint4 u1 = *(const uint4*)(pA + r1*128 + (((4*ch+tg)^((r1&1)<<2)))*16);
                ah[mi][0]=u0.x; ah[mi][1]=u1.x; ah[mi][2]=u0.y; ah[mi][3]=u1.y;
                al[mi][0]=u0.z; al[mi][1]=u1.z; al[mi][2]=u0.w; al[mi][3]=u1.w;
            }
            #pragma unroll
            for (int ni=0;ni<4;ni++){
                int r = wn*32 + ni*8 + lg;
                uint4 bu = *(const uint4*)(pB + r*128 + (((4*ch+tg)^((r&1)<<2)))*16);
                uint32_t bh[2] = {bu.x, bu.y};
                uint32_t bl[2] = {bu.z, bu.w};
                #pragma unroll
                for (int mi=0;mi<4;mi++){
                    mmabf(c[mi][ni], ah[mi], bh);
                    mmabf(c[mi][ni], ah[mi], bl);
                    mmabf(c[mi][ni], al[mi], bh);
                }
            }
        }
    }
    #undef G_ISSUE

    if (mode == 1){
        #pragma unroll
        for (int mi=0;mi<4;mi++)
          #pragma unroll
          for (int half=0; half<2; ++half){
            int token = tok0 + wm*64 + mi*16 + half*8 + lg;
            float* dst = outp + (size_t)token*ND + nt*128 + wn*32;
            #pragma unroll
            for (int ni=0;ni<4;ni++)
                *(float2*)(dst + ni*8 + 2*tg) =
                    make_float2(c[mi][ni][half*2], c[mi][ni][half*2+1]);
          }
        return;
    }

    // ---- mode 0: cross-warp RMS (warp wn pairs with wn^1 over the same head) ----
    __syncthreads();
    float* red = (float*)dsm;              // [128][4]
    float part[4][2];
    #pragma unroll
    for (int mi=0;mi<4;mi++){
        float s0=0.f, s1=0.f;
        #pragma unroll
        for (int ni=0;ni<4;ni++){
            s0 += c[mi][ni][0]*c[mi][ni][0] + c[mi][ni][1]*c[mi][ni][1];
            s1 += c[mi][ni][2]*c[mi][ni][2] + c[mi][ni][3]*c[mi][ni][3];
        }
        s0 += __shfl_xor_sync(0xffffffffu, s0, 1);
        s0 += __shfl_xor_sync(0xffffffffu, s0, 2);
        s1 += __shfl_xor_sync(0xffffffffu, s1, 1);
        s1 += __shfl_xor_sync(0xffffffffu, s1, 2);
        part[mi][0]=s0; part[mi][1]=s1;
        if (tg == 0){
            red[(wm*64 + mi*16 + lg)*4 + wn]     = s0;
            red[(wm*64 + mi*16 + 8 + lg)*4 + wn] = s1;
        }
    }
    __syncthreads();
    float rs[4][2];
    #pragma unroll
    for (int mi=0;mi<4;mi++)
      #pragma unroll
      for (int half=0; half<2; ++half){
        int row = wm*64 + mi*16 + half*8 + lg;
        float tot = part[mi][half] + red[row*4 + (wn^1)];
        rs[mi][half] = rsqrtf(tot*(1.f/64.f) + 1e-6f);
      }

    const int which = nt >> 3;
    const int head = (nt & 7)*2 + (wn >> 1);
    const int dbase = (wn & 1)*32;

    if (which == 2){
        #pragma unroll
        for (int mi=0;mi<4;mi++)
          #pragma unroll
          for (int half=0; half<2; ++half){
            int token = tok0 + wm*64 + mi*16 + half*8 + lg;
            int bb = token >> 11, ss = token & (NS-1);
            float rms = rs[mi][half];
            float* dst = g_V + ((size_t)((bb*NH + head)*NS + ss))*64 + dbase;
            #pragma unroll
            for (int ni=0;ni<4;ni++)
                *(float2*)(dst + ni*8 + 2*tg) =
                    make_float2(tf32r(c[mi][ni][half*2]*rms),
                                tf32r(c[mi][ni][half*2+1]*rms));
          }
    } else {
        const float* sc = (which==0)? qsc : ksc;
        float sc2[4][2];
        #pragma unroll
        for (int ni=0;ni<4;ni++){
            float2 s2 = *(const float2*)(sc + dbase + ni*8 + 2*tg);
            sc2[ni][0]=s2.x; sc2[ni][1]=s2.y;
        }
        uint4* gdst = (which==0)? g_Qp : g_Kp;
        #pragma unroll
        for (int mi=0;mi<4;mi++)
          #pragma unroll
          for (int half=0; half<2; ++half){
            int token = tok0 + wm*64 + mi*16 + half*8 + lg;
            int bb = token >> 11, ss = token & (NS-1);
            float rms = rs[mi][half];
            float vr[4][2];
            #pragma unroll
            for (int ni=0;ni<4;ni++){
                vr[ni][0] = c[mi][ni][half*2]*rms*sc2[ni][0];
                vr[ni][1] = c[mi][ni][half*2+1]*rms*sc2[ni][1];
            }
            const float* cb = cosp + (size_t)token*64 + dbase;
            const float* sb = sinp + (size_t)token*64 + dbase;
            float ov[4][2];
            #pragma unroll
            for (int ni=0;ni<4;ni++){
                float2 cv = *(const float2*)(cb + ni*8 + 2*tg);
                float2 sv = *(const float2*)(sb + ni*8 + 2*tg);
                int par = ni ^ 2;
                float r0 = (ni & 2) ? vr[par][0] : -vr[par][0];
                float r1 = (ni & 2) ? vr[par][1] : -vr[par][1];
                ov[ni][0] = vr[ni][0]*cv.x + r0*sv.x;
                ov[ni][1] = vr[ni][1]*cv.y + r1*sv.y;
            }
            uint4* dst = gdst + ((size_t)((bb*NH + head)*NS + ss))*16;
            #pragma unroll
            for (int cc=0; cc<2; ++cc){
                uint32_t h0,l0,h1,l1;
                bfsplit2(ov[2*cc][0],   ov[2*cc][1],   h0, l0);
                bfsplit2(ov[2*cc+1][0], ov[2*cc+1][1], h1, l1);
                dst[((wn&1)*2 + cc)*4 + tg] = make_uint4(h0, h1, l0, l1);
            }
          }
    }
}

// ---------------------------------------------------------------------------
// flash attention: 64 q rows/block, 4 warps, 3 CTAs/SM (69632B smem).
// K: 2-stage XOR-swizzled 256B rows. V: 2-stage adjacent-paired V^T (288B
// rows). P stays IN REGISTERS: PV a-frag = QK accumulator (adjacent-pair
// V layout makes slot<->key identity hold). ONE barrier per iteration.
// ---------------------------------------------------------------------------
#define AT_V   32768
#define ATTN_SMEM 69632

__global__ void __launch_bounds__(128, 3) attn_kernel()
{
    extern __shared__ __align__(16) char dsm[];

    const int tid = threadIdx.x, lane = tid & 31, w = tid >> 5;
    const int lg = lane >> 2, tg = lane & 3;
    const int qt = blockIdx.x, h = blockIdx.y, b = blockIdx.z;
    const size_t bhrow = (size_t)(b*NH + h)*NS;
    const size_t bh64  = (size_t)(b*NH + h)*64;
    const uint32_t sdyn = smem_u32(dsm);

    // ---- stage Q into K0 region (swizzled 256B rows), extract frags ----
    {
        size_t qrow0 = bhrow + (size_t)qt*64;
        #pragma unroll
        for (int i=0;i<8;i++){
            int idx = i*128 + tid;
            int u = idx&3, cc = (idx>>2)&3, row = idx>>4;
            uint32_t ph = (uint32_t)((4*cc+u) ^ ((row&1)<<2));
            cpa16(sdyn + row*256 + ph*16, g_Qp + (qrow0+row)*16 + cc*4 + u);
        }
        CP_COMMIT(); CP_WAIT(0);
        __syncthreads();
    }
    uint32_t qh[4][4], ql[4][4];
    #pragma unroll
    for (int cc=0; cc<4; ++cc){
        int r0 = w*16 + lg, r1 = r0 + 8;
        uint4 u0 = *(const uint4*)(dsm + r0*256 + (((4*cc+tg)^((r0&1)<<2)))*16);
        uint4 u1 = *(const uint4*)(dsm + r1*256 + (((4*cc+tg)^((r1&1)<<2)))*16);
        qh[cc][0]=u0.x; qh[cc][1]=u1.x; qh[cc][2]=u0.y; qh[cc][3]=u1.y;
        ql[cc][0]=u0.z; ql[cc][1]=u1.z; ql[cc][2]=u0.w; ql[cc][3]=u1.w;
    }
    __syncthreads();

    #define K_ISSUE(kt) do { \
        uint32_t kb = sdyn + ((kt)&1)*16384; \
        size_t krow0 = bhrow + (size_t)(kt)*64; \
        _Pragma("unroll") \
        for (int i=0;i<8;i++){ \
            int idx = i*128 + tid; \
            int u = idx&3, cc = (idx>>2)&3, row = idx>>4; \
            uint32_t ph = (uint32_t)((4*cc+u) ^ ((row&1)<<2)); \
            cpa16(kb + row*256 + ph*16, g_Kp + (krow0+row)*16 + cc*4 + u); \
        } \
        CP_COMMIT(); \
    } while(0)

    #define V_ISSUE(kt) do { \
        uint32_t vb = sdyn + AT_V + ((kt)&1)*18432; \
        _Pragma("unroll") \
        for (int i=0;i<8;i++){ \
            int idx = i*128 + tid; \
            int u16 = idx&15, row = idx>>4; \
            cpa16(vb + row*288 + u16*16, \
                  g_Vt + (bh64 + row)*1024 + (kt)*32 + u16*2); \
        } \
        CP_COMMIT(); \
    } while(0)

    float ofr[8][4];
    #pragma unroll
    for (int ni=0;ni<8;ni++){ ofr[ni][0]=0;ofr[ni][1]=0;ofr[ni][2]=0;ofr[ni][3]=0; }
    float m0=-INFINITY, m1=-INFINITY, l0=0.f, l1=0.f;

    K_ISSUE(0);
    V_ISSUE(0);

    for (int kt=0; kt<NS/64; ++kt){
        CP_WAIT(0);
        __syncthreads();
        if (kt + 1 < NS/64){ K_ISSUE(kt+1); V_ISSUE(kt+1); }

        const char* kb = dsm + (kt&1)*16384;
        const char* vb = dsm + AT_V + (kt&1)*18432;

        // ---- QK^T: bf16x2 3-term ----
        float sfr[8][4];
        #pragma unroll
        for (int ni=0;ni<8;ni++){ sfr[ni][0]=0;sfr[ni][1]=0;sfr[ni][2]=0;sfr[ni][3]=0; }
        #pragma unroll
        for (int ni=0;ni<8;ni++){
            int r = ni*8 + lg;
            #pragma unroll
            for (int cc=0; cc<4; ++cc){
                uint4 bu = *(const uint4*)(kb + r*256 + (((4*cc+tg)^((r&1)<<2)))*16);
                uint32_t bh[2] = {bu.x, bu.y};
                uint32_t bl[2] = {bu.z, bu.w};
                mmabf(sfr[ni], qh[cc], bh);
                mmabf(sfr[ni], qh[cc], bl);
                mmabf(sfr[ni], ql[cc], bh);
            }
        }
        // ---- online softmax ----
        float t0=-INFINITY, t1=-INFINITY;
        #pragma unroll
        for (int ni=0;ni<8;ni++){
            t0 = fmaxf(t0, fmaxf(sfr[ni][0], sfr[ni][1]));
            t1 = fmaxf(t1, fmaxf(sfr[ni][2], sfr[ni][3]));
        }
        t0 = fmaxf(t0, __shfl_xor_sync(0xffffffffu, t0, 1));
        t0 = fmaxf(t0, __shfl_xor_sync(0xffffffffu, t0, 2));
        t1 = fmaxf(t1, __shfl_xor_sync(0xffffffffu, t1, 1));
        t1 = fmaxf(t1, __shfl_xor_sync(0xffffffffu, t1, 2));
        float mn0 = fmaxf(m0, t0), mn1 = fmaxf(m1, t1);
        float a0 = __expf(m0 - mn0), a1 = __expf(m1 - mn1);
        float p0 = 0.f, p1 = 0.f;
        #pragma unroll
        for (int ni=0;ni<8;ni++){
            sfr[ni][0] = __expf(sfr[ni][0]-mn0); p0 += sfr[ni][0];
            sfr[ni][1] = __expf(sfr[ni][1]-mn0); p0 += sfr[ni][1];
            sfr[ni][2] = __expf(sfr[ni][2]-mn1); p1 += sfr[ni][2];
            sfr[ni][3] = __expf(sfr[ni][3]-mn1); p1 += sfr[ni][3];
        }
        p0 += __shfl_xor_sync(0xffffffffu, p0, 1);
        p0 += __shfl_xor_sync(0xffffffffu, p0, 2);
        p1 += __shfl_xor_sync(0xffffffffu, p1, 1);
        p1 += __shfl_xor_sync(0xffffffffu, p1, 2);
        l0 = l0*a0 + p0; l1 = l1*a1 + p1;
        m0 = mn0; m1 = mn1;
        #pragma unroll
        for (int ni=0;ni<8;ni++){
            ofr[ni][0]*=a0; ofr[ni][1]*=a0; ofr[ni][2]*=a1; ofr[ni][3]*=a1;
        }
        // ---- O += P * V : a-frag = QK accumulator registers (no smem P) ----
        // a-slot tg <-> score col 2tg = key k2*8+2tg; slot tg+4 <-> col 2tg+1.
        // V^T pairs adjacent keys {2t, 2t+1} -> b matches by construction.
        #pragma unroll
        for (int k2=0;k2<8;k2++){
            float pa[4] = { tf32r(sfr[k2][0]), tf32r(sfr[k2][2]),
                            tf32r(sfr[k2][1]), tf32r(sfr[k2][3]) };
            #pragma unroll
            for (int ni=0;ni<8;ni++){
                float2 bv2 = *(const float2*)(vb + (ni*8+lg)*288 + (k2*4+tg)*8);
                float bv[2] = {bv2.x, bv2.y};
                mma8(ofr[ni], pa, bv);
            }
        }
    }
    #undef K_ISSUE
    #undef V_ISSUE

    // ---- epilogue: write AO packed bf16 hi/lo ----
    float i0 = 1.f/l0, i1 = 1.f/l1;
    #pragma unroll
    for (int half=0; half<2; ++half){
        int token = b*NS + qt*64 + w*16 + half*8 + lg;
        float inv = half ? i1 : i0;
        float v[8][2];
        #pragma unroll
        for (int ni=0;ni<8;ni++){
            v[ni][0] = ofr[ni][half*2]*inv;
            v[ni][1] = ofr[ni][half*2+1]*inv;
        }
        uint4* dst = g_AOp + ((size_t)token*64 + h*4)*4;
        #pragma unroll
        for (int cc=0; cc<4; ++cc){
            uint32_t h0,l0w,h1,l1w;
            bfsplit2(v[2*cc][0],   v[2*cc][1],   h0, l0w);
            bfsplit2(v[2*cc+1][0], v[2*cc+1][1], h1, l1w);
            dst[cc*4 + tg] = make_uint4(h0, h1, l0w, l1w);
        }
    }
}

// ---------------------------------------------------------------------------
extern "C" void kernel_launch(void* const* d_in, const int* in_sizes, int n_in,
                              void* d_out, int out_size)
{
    (void)in_sizes; (void)n_in; (void)out_size;
    const float* X    = (const float*)d_in[0];
    const float* cosp = (const float*)d_in[1];
    const float* sinp = (const float*)d_in[2];
    // d_in[3] = position_ids (unused by reference)
    const float* wq   = (const float*)d_in[4];
    const float* wk   = (const float*)d_in[5];
    const float* wv   = (const float*)d_in[6];
    const float* wo   = (const float*)d_in[7];
    const float* qsc  = (const float*)d_in[8];
    const float* ksc  = (const float*)d_in[9];
    float* out = (float*)d_out;

    cudaFuncSetAttribute(gemm128,
                         cudaFuncAttributeMaxDynamicSharedMemorySize, GEMM_SMEM);
    cudaFuncSetAttribute(attn_kernel,
                         cudaFuncAttributeMaxDynamicSharedMemorySize, ATTN_SMEM);

    prep_x<<<NTOK*64/256, 256>>>(X);
    prep_w<<<4*ND*64/256, 256>>>(wq, wk, wv, wo);
    gemm128<<<dim3(NTOK/128, 24), 256, GEMM_SMEM>>>(0, cosp, sinp, qsc, ksc, nullptr);
    transp_v<<<dim3(NS/64, NH, NB), 128>>>();
    attn_kernel<<<dim3(NS/64, NH, NB), 128, ATTN_SMEM>>>();
    gemm128<<<dim3(NTOK/128, ND/128), 256, GEMM_SMEM>>>(1, nullptr, nullptr, nullptr, nullptr, out);
}

// round 17
// speedup vs baseline: 1.2624x; 1.0209x over previous
#include <cuda_runtime.h>
#include <cuda_bf16.h>
#include <math.h>
#include <stdint.h>

#define NB 4
#define NS 2048
#define ND 1024
#define NH 16
#define NHD 64
#define NTOK (NB*NS)

// ---------------- device global scratch (allocation-free) ----------------
// packed unit = 16B = {hi pair_t, hi pair_{t+4}, lo pair_t, lo pair_{t+4}}
__device__ uint4 g_Xp [(size_t)NTOK*64*4];        // X packed
__device__ uint4 g_Wp [(size_t)3*ND*64*4];        // wq|wk|wv packed
__device__ uint4 g_WOp[(size_t)ND*64*4];          // wo packed
__device__ uint4 g_Qp [(size_t)NB*NH*NS*16];      // Q packed
__device__ uint4 g_Kp [(size_t)NB*NH*NS*16];      // K packed
__device__ float g_V  [(size_t)NB*NH*NS*NHD];     // V fp32, [bh][s][d]
__device__ float2 g_Vt[(size_t)NB*NH*64*1024];    // V^T adjacent-paired: [bh][d][1024]
__device__ uint4 g_AOp[(size_t)NTOK*64*4];        // attention out packed

// ---------------- helpers ----------------
__device__ __forceinline__ uint32_t smem_u32(const void* p){
    uint32_t a;
    asm("{ .reg .u64 t; cvta.to.shared.u64 t, %1; cvt.u32.u64 %0, t; }" : "=r"(a) : "l"(p));
    return a;
}
__device__ __forceinline__ float tf32r(float x){
    uint32_t y; asm("cvt.rna.tf32.f32 %0, %1;" : "=r"(y) : "f"(x));
    return __uint_as_float(y);
}
__device__ __forceinline__ void mma8(float c[4], const float a[4], const float b[2]){
    asm volatile(
      "mma.sync.aligned.m16n8k8.row.col.f32.tf32.tf32.f32 "
      "{%0,%1,%2,%3}, {%4,%5,%6,%7}, {%8,%9}, {%0,%1,%2,%3};\n"
      : "+f"(c[0]),"+f"(c[1]),"+f"(c[2]),"+f"(c[3])
      : "r"(__float_as_uint(a[0])),"r"(__float_as_uint(a[1])),
        "r"(__float_as_uint(a[2])),"r"(__float_as_uint(a[3])),
        "r"(__float_as_uint(b[0])),"r"(__float_as_uint(b[1])));
}
__device__ __forceinline__ void mmabf(float c[4], const uint32_t a[4], const uint32_t b[2]){
    asm volatile(
      "mma.sync.aligned.m16n8k16.row.col.f32.bf16.bf16.f32 "
      "{%0,%1,%2,%3}, {%4,%5,%6,%7}, {%8,%9}, {%0,%1,%2,%3};\n"
      : "+f"(c[0]),"+f"(c[1]),"+f"(c[2]),"+f"(c[3])
      : "r"(a[0]),"r"(a[1]),"r"(a[2]),"r"(a[3]), "r"(b[0]),"r"(b[1]));
}
__device__ __forceinline__ void cpa16(uint32_t saddr, const void* gaddr){
    asm volatile("cp.async.cg.shared.global [%0], [%1], 16;" :: "r"(saddr), "l"(gaddr) : "memory");
}
#define CP_COMMIT() asm volatile("cp.async.commit_group;" ::: "memory")
#define CP_WAIT(n)  asm volatile("cp.async.wait_group %0;" :: "n"(n) : "memory")

__device__ __forceinline__ uint32_t packbf2(__nv_bfloat16 a, __nv_bfloat16 b){
    return (uint32_t)__bfloat16_as_ushort(a) | ((uint32_t)__bfloat16_as_ushort(b) << 16);
}
__device__ __forceinline__ void bfsplit2(float a, float b, uint32_t& hi, uint32_t& lo){
    __nv_bfloat16 ha = __float2bfloat16(a), hb = __float2bfloat16(b);
    hi = packbf2(ha, hb);
    lo = packbf2(__float2bfloat16(a - __bfloat162float(ha)),
                 __float2bfloat16(b - __bfloat162float(hb)));
}

// ---------------------------------------------------------------------------
// prep: one thread packs one k16 chunk
// ---------------------------------------------------------------------------
__device__ __forceinline__ void pack_chunk(const float* src, uint4* dst){
    float x[16];
    #pragma unroll
    for (int i=0;i<4;i++){ float4 v = *(const float4*)(src + i*4);
        x[i*4]=v.x; x[i*4+1]=v.y; x[i*4+2]=v.z; x[i*4+3]=v.w; }
    uint32_t hi[8], lo[8];
    #pragma unroll
    for (int j=0;j<8;j++) bfsplit2(x[2*j], x[2*j+1], hi[j], lo[j]);
    #pragma unroll
    for (int u=0;u<4;u++) dst[u] = make_uint4(hi[u], hi[u+4], lo[u], lo[u+4]);
}

__global__ __launch_bounds__(256) void prep_x(const float* __restrict__ X){
    int i = blockIdx.x*256 + threadIdx.x;
    pack_chunk(X + (size_t)i*16, g_Xp + (size_t)i*4);
}

__global__ __launch_bounds__(256) void prep_w(
    const float* __restrict__ wq, const float* __restrict__ wk,
    const float* __restrict__ wv, const float* __restrict__ wo){
    int i = blockIdx.x*256 + threadIdx.x;
    if (i < 3*ND*64){
        int row = i >> 6, c = i & 63;
        int which = row >> 10, r = row & 1023;
        const float* src = (which==0)? wq : (which==1)? wk : wv;
        pack_chunk(src + (size_t)r*ND + c*16, g_Wp + (size_t)i*4);
    } else {
        int j = i - 3*ND*64;
        int row = j >> 6, c = j & 63;
        pack_chunk(wo + (size_t)row*ND + c*16, g_WOp + (size_t)j*4);
    }
}

// ---------------------------------------------------------------------------
// V transpose: g_V [bh][s][d] -> g_Vt [bh][d] with ADJACENT pairing
// ---------------------------------------------------------------------------
__global__ __launch_bounds__(128) void transp_v(){
    __shared__ float Vs[64*65];
    const int tid = threadIdx.x;
    const int t3 = blockIdx.x, h = blockIdx.y, b = blockIdx.z;
    const size_t bh = (size_t)(b*NH + h);
    const float* src = g_V + (bh*NS + (size_t)t3*64)*64;
    #pragma unroll
    for (int i=0;i<8;i++){
        int idx = i*128 + tid, row = idx>>4, c4 = idx&15;
        float4 v = *(const float4*)(src + row*64 + c4*4);
        Vs[row*65 + c4*4+0]=v.x; Vs[row*65 + c4*4+1]=v.y;
        Vs[row*65 + c4*4+2]=v.z; Vs[row*65 + c4*4+3]=v.w;
    }
    __syncthreads();
    float2* dst = g_Vt + bh*64*1024;
    #pragma unroll
    for (int i=0;i<16;i++){
        int idx = i*128 + tid;
        int t = idx&3, jl = (idx>>2)&7, d = idx>>5;
        int s = jl*8 + 2*t;
        dst[(size_t)d*1024 + (t3*8 + jl)*4 + t] =
            make_float2(Vs[s*65 + d], Vs[(s+1)*65 + d]);
    }
}

// ---------------------------------------------------------------------------
// GEMM: C[128x64] = A[128x1024] * B[64x1024]^T, bf16x2 3-term.
// 4 warps (128 thr), warp tile 64x32 (wm=w>>1, wn=w&1). 2-stage cp.async,
// k-tile=32, XOR-swizzled 128B rows. Stage = 24576B (A 16K + B 8K);
// 2 stages = 48KB -> 4 CTAs/SM (16 warps, cross-CTA latency overlap).
// mode 0: grid y=48 (nt = which*16 + head), RMS(+scale)+RoPE epilogue
// mode 1: grid y=16, plain store
// ---------------------------------------------------------------------------
#define GSTAGE 24576
#define GEMM_SMEM (2*GSTAGE)

__global__ void __launch_bounds__(128, 4) gemm128(
    int mode,
    const float* __restrict__ cosp, const float* __restrict__ sinp,
    const float* __restrict__ qsc,  const float* __restrict__ ksc,
    float* __restrict__ outp)
{
    extern __shared__ __align__(16) char dsm[];
    const int tid = threadIdx.x, lane = tid & 31, w = tid >> 5;
    const int lg = lane >> 2, tg = lane & 3;
    const int wm = w >> 1, wn = w & 1;
    const int tok0 = blockIdx.x * 128;
    const int nt = blockIdx.y;
    const int brow0 = nt * 64;
    const uint32_t sdyn = smem_u32(dsm);

    const uint4* Aunits = mode ? g_AOp : g_Xp;
    const uint4* Bunits = mode ? g_WOp : g_Wp;

    float c[4][4][4];
    #pragma unroll
    for (int mi=0;mi<4;mi++)
      #pragma unroll
      for (int ni=0;ni<4;ni++)
        #pragma unroll
        for (int q=0;q<4;q++) c[mi][ni][q]=0.f;

    // issue one k32 tile into stage (ck & 1): A 8 units/thread, B 4/thread
    #define G_ISSUE(ck) do { \
        uint32_t sa = sdyn + ((ck)&1)*GSTAGE; \
        uint32_t sb = sa + 16384; \
        int ck2 = (ck)*2; \
        _Pragma("unroll") \
        for (int i=0;i<8;i++){ \
            int idx = i*128 + tid; \
            int u = idx&7, row = idx>>3; \
            uint32_t ph = (uint32_t)(u ^ ((row&1)<<2)); \
            int chk = ck2 + (u>>2), ui = u&3; \
            cpa16(sa + row*128 + ph*16, \
                  Aunits + ((size_t)(tok0+row)*64 + chk)*4 + ui); \
        } \
        _Pragma("unroll") \
        for (int i=0;i<4;i++){ \
            int idx = i*128 + tid; \
            int u = idx&7, row = idx>>3; \
            uint32_t ph = (uint32_t)(u ^ ((row&1)<<2)); \
            int chk = ck2 + (u>>2), ui = u&3; \
            cpa16(sb + row*128 + ph*16, \
                  Bunits + ((size_t)(brow0+row)*64 + chk)*4 + ui); \
        } \
        CP_COMMIT(); \
    } while(0)

    G_ISSUE(0);
    for (int ck = 0; ck < 32; ++ck){
        if (ck < 31){ G_ISSUE(ck+1); CP_WAIT(1); }
        else        { CP_WAIT(0); }
        __syncthreads();
        const char* pA = dsm + (ck&1)*GSTAGE;
        const char* pB = pA + 16384;
        #pragma unroll
        for (int ch=0; ch<2; ++ch){
            uint32_t ah[4][4], al[4][4];
            #pragma unroll
            for (int mi=0;mi<4;mi++){
                int r0 = wm*64 + mi*16 + lg, r1 = r0 + 8;
                uint4 u0 = *(const uint4*)(pA + r0*128 + (((4*ch+tg)^((r0&1)<<2)))*16);
                uint4 u1 = *(const uint4*)(pA + r1*128 + (((4*ch+tg)^((r1&1)<<2)))*16);
                ah[mi][0]=u0.x; ah[mi][1]=u1.x; ah[mi][2]=u0.y; ah[mi][3]=u1.y;
                al[mi][0]=u0.z; al[mi][1]=u1.z; al[mi][2]=u0.w; al[mi][3]=u1.w;
            }
            #pragma unroll
            for (int ni=0;ni<4;ni++){
                int r = wn*32 + ni*8 + lg;
                uint4 bu = *(const uint4*)(pB + r*128 + (((4*ch+tg)^((r&1)<<2)))*16);
                uint32_t bh[2] = {bu.x, bu.y};
                uint32_t bl[2] = {bu.z, bu.w};
                #pragma unroll
                for (int mi=0;mi<4;mi++){
                    mmabf(c[mi][ni], ah[mi], bh);
                    mmabf(c[mi][ni], ah[mi], bl);
                    mmabf(c[mi][ni], al[mi], bh);
                }
            }
        }
        __syncthreads();
    }
    #undef G_ISSUE

    if (mode == 1){
        #pragma unroll
        for (int mi=0;mi<4;mi++)
          #pragma unroll
          for (int half=0; half<2; ++half){
            int token = tok0 + wm*64 + mi*16 + half*8 + lg;
            float* dst = outp + (size_t)token*ND + nt*64 + wn*32;
            #pragma unroll
            for (int ni=0;ni<4;ni++)
                *(float2*)(dst + ni*8 + 2*tg) =
                    make_float2(c[mi][ni][half*2], c[mi][ni][half*2+1]);
          }
        return;
    }

    // ---- mode 0: cross-warp RMS (warp wn pairs with wn^1; one head per CTA) ----
    float* red = (float*)dsm;              // [128][2]
    float part[4][2];
    #pragma unroll
    for (int mi=0;mi<4;mi++){
        float s0=0.f, s1=0.f;
        #pragma unroll
        for (int ni=0;ni<4;ni++){
            s0 += c[mi][ni][0]*c[mi][ni][0] + c[mi][ni][1]*c[mi][ni][1];
            s1 += c[mi][ni][2]*c[mi][ni][2] + c[mi][ni][3]*c[mi][ni][3];
        }
        s0 += __shfl_xor_sync(0xffffffffu, s0, 1);
        s0 += __shfl_xor_sync(0xffffffffu, s0, 2);
        s1 += __shfl_xor_sync(0xffffffffu, s1, 1);
        s1 += __shfl_xor_sync(0xffffffffu, s1, 2);
        part[mi][0]=s0; part[mi][1]=s1;
        if (tg == 0){
            red[(wm*64 + mi*16 + lg)*2 + wn]     = s0;
            red[(wm*64 + mi*16 + 8 + lg)*2 + wn] = s1;
        }
    }
    __syncthreads();
    float rs[4][2];
    #pragma unroll
    for (int mi=0;mi<4;mi++)
      #pragma unroll
      for (int half=0; half<2; ++half){
        int row = wm*64 + mi*16 + half*8 + lg;
        float tot = part[mi][half] + red[row*2 + (wn^1)];
        rs[mi][half] = rsqrtf(tot*(1.f/64.f) + 1e-6f);
      }

    const int which = nt >> 4;
    const int head = nt & 15;
    const int dbase = wn*32;

    if (which == 2){
        #pragma unroll
        for (int mi=0;mi<4;mi++)
          #pragma unroll
          for (int half=0; half<2; ++half){
            int token = tok0 + wm*64 + mi*16 + half*8 + lg;
            int bb = token >> 11, ss = token & (NS-1);
            float rms = rs[mi][half];
            float* dst = g_V + ((size_t)((bb*NH + head)*NS + ss))*64 + dbase;
            #pragma unroll
            for (int ni=0;ni<4;ni++)
                *(float2*)(dst + ni*8 + 2*tg) =
                    make_float2(tf32r(c[mi][ni][half*2]*rms),
                                tf32r(c[mi][ni][half*2+1]*rms));
          }
    } else {
        const float* sc = (which==0)? qsc : ksc;
        float sc2[4][2];
        #pragma unroll
        for (int ni=0;ni<4;ni++){
            float2 s2 = *(const float2*)(sc + dbase + ni*8 + 2*tg);
            sc2[ni][0]=s2.x; sc2[ni][1]=s2.y;
        }
        uint4* gdst = (which==0)? g_Qp : g_Kp;
        #pragma unroll
        for (int mi=0;mi<4;mi++)
          #pragma unroll
          for (int half=0; half<2; ++half){
            int token = tok0 + wm*64 + mi*16 + half*8 + lg;
            int bb = token >> 11, ss = token & (NS-1);
            float rms = rs[mi][half];
            float vr[4][2];
            #pragma unroll
            for (int ni=0;ni<4;ni++){
                vr[ni][0] = c[mi][ni][half*2]*rms*sc2[ni][0];
                vr[ni][1] = c[mi][ni][half*2+1]*rms*sc2[ni][1];
            }
            const float* cb = cosp + (size_t)token*64 + dbase;
            const float* sb = sinp + (size_t)token*64 + dbase;
            float ov[4][2];
            #pragma unroll
            for (int ni=0;ni<4;ni++){
                float2 cv = *(const float2*)(cb + ni*8 + 2*tg);
                float2 sv = *(const float2*)(sb + ni*8 + 2*tg);
                int par = ni ^ 2;
                float r0 = (ni & 2) ? vr[par][0] : -vr[par][0];
                float r1 = (ni & 2) ? vr[par][1] : -vr[par][1];
                ov[ni][0] = vr[ni][0]*cv.x + r0*sv.x;
                ov[ni][1] = vr[ni][1]*cv.y + r1*sv.y;
            }
            uint4* dst = gdst + ((size_t)((bb*NH + head)*NS + ss))*16;
            #pragma unroll
            for (int cc=0; cc<2; ++cc){
                uint32_t h0,l0,h1,l1;
                bfsplit2(ov[2*cc][0],   ov[2*cc][1],   h0, l0);
                bfsplit2(ov[2*cc+1][0], ov[2*cc+1][1], h1, l1);
                dst[(wn*2 + cc)*4 + tg] = make_uint4(h0, h1, l0, l1);
            }
          }
    }
}

// ---------------------------------------------------------------------------
// flash attention: 64 q rows/block, 4 warps, 3 CTAs/SM (69632B smem).
// (byte-identical to passing round-16 version: register-resident P)
// ---------------------------------------------------------------------------
#define AT_V   32768
#define ATTN_SMEM 69632

__global__ void __launch_bounds__(128, 3) attn_kernel()
{
    extern __shared__ __align__(16) char dsm[];

    const int tid = threadIdx.x, lane = tid & 31, w = tid >> 5;
    const int lg = lane >> 2, tg = lane & 3;
    const int qt = blockIdx.x, h = blockIdx.y, b = blockIdx.z;
    const size_t bhrow = (size_t)(b*NH + h)*NS;
    const size_t bh64  = (size_t)(b*NH + h)*64;
    const uint32_t sdyn = smem_u32(dsm);

    // ---- stage Q into K0 region (swizzled 256B rows), extract frags ----
    {
        size_t qrow0 = bhrow + (size_t)qt*64;
        #pragma unroll
        for (int i=0;i<8;i++){
            int idx = i*128 + tid;
            int u = idx&3, cc = (idx>>2)&3, row = idx>>4;
            uint32_t ph = (uint32_t)((4*cc+u) ^ ((row&1)<<2));
            cpa16(sdyn + row*256 + ph*16, g_Qp + (qrow0+row)*16 + cc*4 + u);
        }
        CP_COMMIT(); CP_WAIT(0);
        __syncthreads();
    }
    uint32_t qh[4][4], ql[4][4];
    #pragma unroll
    for (int cc=0; cc<4; ++cc){
        int r0 = w*16 + lg, r1 = r0 + 8;
        uint4 u0 = *(const uint4*)(dsm + r0*256 + (((4*cc+tg)^((r0&1)<<2)))*16);
        uint4 u1 = *(const uint4*)(dsm + r1*256 + (((4*cc+tg)^((r1&1)<<2)))*16);
        qh[cc][0]=u0.x; qh[cc][1]=u1.x; qh[cc][2]=u0.y; qh[cc][3]=u1.y;
        ql[cc][0]=u0.z; ql[cc][1]=u1.z; ql[cc][2]=u0.w; ql[cc][3]=u1.w;
    }
    __syncthreads();

    #define K_ISSUE(kt) do { \
        uint32_t kb = sdyn + ((kt)&1)*16384; \
        size_t krow0 = bhrow + (size_t)(kt)*64; \
        _Pragma("unroll") \
        for (int i=0;i<8;i++){ \
            int idx = i*128 + tid; \
            int u = idx&3, cc = (idx>>2)&3, row = idx>>4; \
            uint32_t ph = (uint32_t)((4*cc+u) ^ ((row&1)<<2)); \
            cpa16(kb + row*256 + ph*16, g_Kp + (krow0+row)*16 + cc*4 + u); \
        } \
        CP_COMMIT(); \
    } while(0)

    #define V_ISSUE(kt) do { \
        uint32_t vb = sdyn + AT_V + ((kt)&1)*18432; \
        _Pragma("unroll") \
        for (int i=0;i<8;i++){ \
            int idx = i*128 + tid; \
            int u16 = idx&15, row = idx>>4; \
            cpa16(vb + row*288 + u16*16, \
                  g_Vt + (bh64 + row)*1024 + (kt)*32 + u16*2); \
        } \
        CP_COMMIT(); \
    } while(0)

    float ofr[8][4];
    #pragma unroll
    for (int ni=0;ni<8;ni++){ ofr[ni][0]=0;ofr[ni][1]=0;ofr[ni][2]=0;ofr[ni][3]=0; }
    float m0=-INFINITY, m1=-INFINITY, l0=0.f, l1=0.f;

    K_ISSUE(0);
    V_ISSUE(0);

    for (int kt=0; kt<NS/64; ++kt){
        CP_WAIT(0);
        __syncthreads();
        if (kt + 1 < NS/64){ K_ISSUE(kt+1); V_ISSUE(kt+1); }

        const char* kb = dsm + (kt&1)*16384;
        const char* vb = dsm + AT_V + (kt&1)*18432;

        // ---- QK^T: bf16x2 3-term ----
        float sfr[8][4];
        #pragma unroll
        for (int ni=0;ni<8;ni++){ sfr[ni][0]=0;sfr[ni][1]=0;sfr[ni][2]=0;sfr[ni][3]=0; }
        #pragma unroll
        for (int ni=0;ni<8;ni++){
            int r = ni*8 + lg;
            #pragma unroll
            for (int cc=0; cc<4; ++cc){
                uint4 bu = *(const uint4*)(kb + r*256 + (((4*cc+tg)^((r&1)<<2)))*16);
                uint32_t bh[2] = {bu.x, bu.y};
                uint32_t bl[2] = {bu.z, bu.w};
                mmabf(sfr[ni], qh[cc], bh);
                mmabf(sfr[ni], qh[cc], bl);
                mmabf(sfr[ni], ql[cc], bh);
            }
        }
        // ---- online softmax ----
        float t0=-INFINITY, t1=-INFINITY;
        #pragma unroll
        for (int ni=0;ni<8;ni++){
            t0 = fmaxf(t0, fmaxf(sfr[ni][0], sfr[ni][1]));
            t1 = fmaxf(t1, fmaxf(sfr[ni][2], sfr[ni][3]));
        }
        t0 = fmaxf(t0, __shfl_xor_sync(0xffffffffu, t0, 1));
        t0 = fmaxf(t0, __shfl_xor_sync(0xffffffffu, t0, 2));
        t1 = fmaxf(t1, __shfl_xor_sync(0xffffffffu, t1, 1));
        t1 = fmaxf(t1, __shfl_xor_sync(0xffffffffu, t1, 2));
        float mn0 = fmaxf(m0, t0), mn1 = fmaxf(m1, t1);
        float a0 = __expf(m0 - mn0), a1 = __expf(m1 - mn1);
        float p0 = 0.f, p1 = 0.f;
        #pragma unroll
        for (int ni=0;ni<8;ni++){
            sfr[ni][0] = __expf(sfr[ni][0]-mn0); p0 += sfr[ni][0];
            sfr[ni][1] = __expf(sfr[ni][1]-mn0); p0 += sfr[ni][1];
            sfr[ni][2] = __expf(sfr[ni][2]-mn1); p1 += sfr[ni][2];
            sfr[ni][3] = __expf(sfr[ni][3]-mn1); p1 += sfr[ni][3];
        }
        p0 += __shfl_xor_sync(0xffffffffu, p0, 1);
        p0 += __shfl_xor_sync(0xffffffffu, p0, 2);
        p1 += __shfl_xor_sync(0xffffffffu, p1, 1);
        p1 += __shfl_xor_sync(0xffffffffu, p1, 2);
        l0 = l0*a0 + p0; l1 = l1*a1 + p1;
        m0 = mn0; m1 = mn1;
        #pragma unroll
        for (int ni=0;ni<8;ni++){
            ofr[ni][0]*=a0; ofr[ni][1]*=a0; ofr[ni][2]*=a1; ofr[ni][3]*=a1;
        }
        // ---- O += P * V : a-frag = QK accumulator registers (no smem P) ----
        #pragma unroll
        for (int k2=0;k2<8;k2++){
            float pa[4] = { tf32r(sfr[k2][0]), tf32r(sfr[k2][2]),
                            tf32r(sfr[k2][1]), tf32r(sfr[k2][3]) };
            #pragma unroll
            for (int ni=0;ni<8;ni++){
                float2 bv2 = *(const float2*)(vb + (ni*8+lg)*288 + (k2*4+tg)*8);
                float bv[2] = {bv2.x, bv2.y};
                mma8(ofr[ni], pa, bv);
            }
        }
    }
    #undef K_ISSUE
    #undef V_ISSUE

    // ---- epilogue: write AO packed bf16 hi/lo ----
    float i0 = 1.f/l0, i1 = 1.f/l1;
    #pragma unroll
    for (int half=0; half<2; ++half){
        int token = b*NS + qt*64 + w*16 + half*8 + lg;
        float inv = half ? i1 : i0;
        float v[8][2];
        #pragma unroll
        for (int ni=0;ni<8;ni++){
            v[ni][0] = ofr[ni][half*2]*inv;
            v[ni][1] = ofr[ni][half*2+1]*inv;
        }
        uint4* dst = g_AOp + ((size_t)token*64 + h*4)*4;
        #pragma unroll
        for (int cc=0; cc<4; ++cc){
            uint32_t h0,l0w,h1,l1w;
            bfsplit2(v[2*cc][0],   v[2*cc][1],   h0, l0w);
            bfsplit2(v[2*cc+1][0], v[2*cc+1][1], h1, l1w);
            dst[cc*4 + tg] = make_uint4(h0, h1, l0w, l1w);
        }
    }
}

// ---------------------------------------------------------------------------
extern "C" void kernel_launch(void* const* d_in, const int* in_sizes, int n_in,
                              void* d_out, int out_size)
{
    (void)in_sizes; (void)n_in; (void)out_size;
    const float* X    = (const float*)d_in[0];
    const float* cosp = (const float*)d_in[1];
    const float* sinp = (const float*)d_in[2];
    // d_in[3] = position_ids (unused by reference)
    const float* wq   = (const float*)d_in[4];
    const float* wk   = (const float*)d_in[5];
    const float* wv   = (const float*)d_in[6];
    const float* wo   = (const float*)d_in[7];
    const float* qsc  = (const float*)d_in[8];
    const float* ksc  = (const float*)d_in[9];
    float* out = (float*)d_out;

    cudaFuncSetAttribute(gemm128,
                         cudaFuncAttributeMaxDynamicSharedMemorySize, GEMM_SMEM);
    cudaFuncSetAttribute(attn_kernel,
                         cudaFuncAttributeMaxDynamicSharedMemorySize, ATTN_SMEM);

    prep_x<<<NTOK*64/256, 256>>>(X);
    prep_w<<<4*ND*64/256, 256>>>(wq, wk, wv, wo);
    gemm128<<<dim3(NTOK/128, 48), 128, GEMM_SMEM>>>(0, cosp, sinp, qsc, ksc, nullptr);
    transp_v<<<dim3(NS/64, NH, NB), 128>>>();
    attn_kernel<<<dim3(NS/64, NH, NB), 128, ATTN_SMEM>>>();
    gemm128<<<dim3(NTOK/128, ND/64), 128, GEMM_SMEM>>>(1, nullptr, nullptr, nullptr, nullptr, out);
}